// round 11
// baseline (speedup 1.0000x reference)
#include <cuda_runtime.h>
#include <math.h>

#define BB 16
#define TT 1024
#define DDIM 512
#define BT (BB*TT)
#define PER ((long)BT*DDIM)

__device__ float g_scratch[13L*PER + 16777216L + 2L*262144L];
__device__ float g_prev[4][BB*DDIM];   // 4-slot sentinel ring

__device__ __forceinline__ float sigf(float x) { return 1.f / (1.f + expf(-x)); }
__device__ __forceinline__ void cp16(unsigned saddr, const void* g) {
    asm volatile("cp.async.ca.shared.global [%0], [%1], 16;" :: "r"(saddr), "l"(g));
}
#define FMA2(a,b,c) asm("fma.rn.f32x2 %0, %1, %2, %0;" : "+l"(a) : "l"(b), "l"(c))
#define DUP2(o,x)   asm("mov.b64 %0, {%1,%1};" : "=l"(o) : "r"(__float_as_uint(x)))
#define PACK2(o,lo,hi) asm("mov.b64 %0, {%1,%2};" : "=l"(o) : "r"(__float_as_uint(lo)), "r"(__float_as_uint(hi)))
#define UNPACK2(lo,hi,a) do { unsigned _l,_h; \
    asm("mov.b64 {%0,%1}, %2;" : "=r"(_l), "=r"(_h) : "l"(a)); \
    lo = __uint_as_float(_l); hi = __uint_as_float(_h); } while(0)

__global__ void init_k() {
    int tid = blockIdx.x * blockDim.x + threadIdx.x;   // 32768 threads
    if (tid < 4 * BB * DDIM)
        g_prev[tid >> 13][tid & 8191] = (tid < BB * DDIM) ? 0.f : -1.f;
}

// in [Z,R,C] -> out [Z,C,R]
__global__ void transpose_k(const float* __restrict__ in, float* __restrict__ out,
                            int R, int C, long sIn, long sOut) {
    __shared__ float tile[32][33];
    const float* ib = in  + (long)blockIdx.z * sIn;
    float*       ob = out + (long)blockIdx.z * sOut;
    int c0 = blockIdx.x * 32, r0 = blockIdx.y * 32;
    for (int i = threadIdx.y; i < 32; i += 8)
        tile[i][threadIdx.x] = ib[(long)(r0 + i) * C + c0 + threadIdx.x];
    __syncthreads();
    for (int i = threadIdx.y; i < 32; i += 8)
        ob[(long)(c0 + i) * R + r0 + threadIdx.x] = tile[threadIdx.x][i];
}

__global__ void softmax1024(float* __restrict__ data) {
    __shared__ float red[8];
    int tid = threadIdx.x;
    float4* p = ((float4*)data) + ((long)blockIdx.x << 8);
    float4 v = p[tid];
    float m = fmaxf(fmaxf(v.x, v.y), fmaxf(v.z, v.w));
    #pragma unroll
    for (int o = 16; o; o >>= 1) m = fmaxf(m, __shfl_xor_sync(0xffffffffu, m, o));
    if ((tid & 31) == 0) red[tid >> 5] = m;
    __syncthreads();
    m = red[0];
    #pragma unroll
    for (int i = 1; i < 8; i++) m = fmaxf(m, red[i]);
    v.x = __expf(v.x - m); v.y = __expf(v.y - m);
    v.z = __expf(v.z - m); v.w = __expf(v.w - m);
    float s = v.x + v.y + v.z + v.w;
    #pragma unroll
    for (int o = 16; o; o >>= 1) s += __shfl_xor_sync(0xffffffffu, s, o);
    __syncthreads();
    if ((tid & 31) == 0) red[tid >> 5] = s;
    __syncthreads();
    s = red[0];
    #pragma unroll
    for (int i = 1; i < 8; i++) s += red[i];
    float inv = 1.f / s;
    v.x *= inv; v.y *= inv; v.z *= inv; v.w *= inv;
    p[tid] = v;
}

// ---------------------------------------------------------------------------
// tf32 tensor-core NT GEMM, cp.async 3-stage pipeline (unchanged from R10).
// ---------------------------------------------------------------------------
#define TSTRIDE 20
#define TSLOT (128 * TSTRIDE)
#define GSMEM (6 * TSLOT * 4)

template<int EPI>
__global__ __launch_bounds__(256)
void tgemm(const float* __restrict__ A, const float* __restrict__ Bw,
           const float* __restrict__ bias,
           const float* __restrict__ aux1, const float* __restrict__ aux2,
           float* __restrict__ C,
           int K, int ldb, int N, long sA, long sB, long sC, float scale)
{
    extern __shared__ float smem[];
    float* AsBase = smem;
    float* BsBase = smem + 3 * TSLOT;
    const int tid  = threadIdx.x;
    const int lane = tid & 31, warp = tid >> 5;
    const int wm = warp >> 2, wn = warp & 3;
    const int g = lane >> 2, t = lane & 3;
    const float* Ab = A  + (long)blockIdx.z * sA + (long)blockIdx.y * 128 * K;
    const float* Bb = Bw + (long)blockIdx.z * sB + (long)blockIdx.x * 128 * ldb;
    const int lr = tid >> 2, lc = (tid & 3) << 2;

    float acc[4][4][4];
    #pragma unroll
    for (int i = 0; i < 4; i++)
        #pragma unroll
        for (int j = 0; j < 4; j++)
            #pragma unroll
            for (int q = 0; q < 4; q++) acc[i][j][q] = 0.f;

    auto ISSUE = [&](int s, int kt) {
        float* As = AsBase + s * TSLOT;
        float* Bs = BsBase + s * TSLOT;
        cp16((unsigned)__cvta_generic_to_shared(&As[lr * TSTRIDE + lc]),
             &Ab[(long)lr * K + kt + lc]);
        cp16((unsigned)__cvta_generic_to_shared(&As[(lr + 64) * TSTRIDE + lc]),
             &Ab[(long)(lr + 64) * K + kt + lc]);
        cp16((unsigned)__cvta_generic_to_shared(&Bs[lr * TSTRIDE + lc]),
             &Bb[(long)lr * ldb + kt + lc]);
        cp16((unsigned)__cvta_generic_to_shared(&Bs[(lr + 64) * TSTRIDE + lc]),
             &Bb[(long)(lr + 64) * ldb + kt + lc]);
        asm volatile("cp.async.commit_group;" ::: "memory");
    };

    auto MM = [&](int s) {
        const float* As = AsBase + s * TSLOT;
        const float* Bs = BsBase + s * TSLOT;
        #pragma unroll
        for (int c = 0; c < 2; c++) {
            const int k0 = c * 8 + t;
            unsigned af[4][4], bf[4][2];
            #pragma unroll
            for (int i = 0; i < 4; i++) {
                const int m = wm * 64 + i * 16 + g;
                af[i][0] = __float_as_uint(As[m * TSTRIDE + k0]);
                af[i][1] = __float_as_uint(As[(m + 8) * TSTRIDE + k0]);
                af[i][2] = __float_as_uint(As[m * TSTRIDE + k0 + 4]);
                af[i][3] = __float_as_uint(As[(m + 8) * TSTRIDE + k0 + 4]);
            }
            #pragma unroll
            for (int j = 0; j < 4; j++) {
                const int n = wn * 32 + j * 8 + g;
                bf[j][0] = __float_as_uint(Bs[n * TSTRIDE + k0]);
                bf[j][1] = __float_as_uint(Bs[n * TSTRIDE + k0 + 4]);
            }
            #pragma unroll
            for (int i = 0; i < 4; i++)
                #pragma unroll
                for (int j = 0; j < 4; j++)
                    asm volatile(
                        "mma.sync.aligned.m16n8k8.row.col.f32.tf32.tf32.f32 "
                        "{%0,%1,%2,%3}, {%4,%5,%6,%7}, {%8,%9}, {%0,%1,%2,%3};\n"
                        : "+f"(acc[i][j][0]), "+f"(acc[i][j][1]),
                          "+f"(acc[i][j][2]), "+f"(acc[i][j][3])
                        : "r"(af[i][0]), "r"(af[i][1]), "r"(af[i][2]), "r"(af[i][3]),
                          "r"(bf[j][0]), "r"(bf[j][1]));
        }
    };

    const int nt = K >> 4;
    ISSUE(0, 0);
    ISSUE(1, 16);
    for (int tt = 0; tt < nt; tt++) {
        if (tt < nt - 1)
            asm volatile("cp.async.wait_group 1;" ::: "memory");
        else
            asm volatile("cp.async.wait_group 0;" ::: "memory");
        __syncthreads();
        MM(tt % 3);
        if (tt + 2 < nt) ISSUE((tt + 2) % 3, (tt + 2) * 16);
    }

    const int gn_base = blockIdx.x * 128 + wn * 32;
    #pragma unroll
    for (int i = 0; i < 4; i++) {
        const long m = (long)blockIdx.y * 128 + wm * 64 + i * 16 + g;
        #pragma unroll
        for (int j = 0; j < 4; j++) {
            const int n0 = gn_base + j * 8 + 2 * t;
            const float b0 = bias ? bias[n0]     : 0.f;
            const float b1 = bias ? bias[n0 + 1] : 0.f;
            const long i0 = (long)blockIdx.z * sC + m * N + n0;
            const long i2 = i0 + 8L * N;
            float x[4] = { acc[i][j][0] * scale + b0, acc[i][j][1] * scale + b1,
                           acc[i][j][2] * scale + b0, acc[i][j][3] * scale + b1 };
            const long idx[4] = { i0, i0 + 1, i2, i2 + 1 };
            float o[4];
            #pragma unroll
            for (int q = 0; q < 4; q++) {
                float xv = x[q];
                if (EPI == 0)      o[q] = xv;
                else if (EPI == 1) o[q] = xv * sigf(xv);
                else if (EPI == 2) o[q] = sigf(xv);
                else if (EPI == 3) o[q] = sigf(xv) * aux1[idx[q]];
                else if (EPI == 4) { float y = xv + aux1[idx[q]]; o[q] = y * sigf(y); }
                else { float s_ = sigf(xv); o[q] = s_ * aux1[idx[q]] + (1.f - s_) * aux2[idx[q]]; }
            }
            float2 w0 = { o[0], o[1] }, w1 = { o[2], o[3] };
            *(float2*)&C[i0] = w0;
            *(float2*)&C[i2] = w1;
        }
    }
}

// ---------------------------------------------------------------------------
// EMA recurrence: 128 CTAs x 256 thr, sentinel-polled 4-slot state ring.
// No atomics/flags. Poll = load: each thread polls its 8 float4 of the state
// (valid iff > -0.5; sigmoid outputs and init 0 qualify), stages into smem.
// Weight row-pairs pre-packed for fma.rn.f32x2 (halves the FMA stream).
// Slot lifecycle: written t-1, read t, owner-reset t+2, rewritten t+3.
// ---------------------------------------------------------------------------
__global__ __launch_bounds__(256, 1)
void ema_rec(const float* __restrict__ bin, const float* __restrict__ pa,
             const float* __restrict__ pd, const float* __restrict__ Wa,
             const float* __restrict__ Wd, float* __restrict__ ema)
{
    __shared__ float prev_s[16 * 512];
    __shared__ float dot_s[8 * 16];
    const int tid  = threadIdx.x;
    const int lane = tid & 31, warp = tid >> 5;
    const int j0 = blockIdx.x * 4;
    const int b0 = warp * 2;
    const int er = tid >> 4, eb = tid & 15;
    float4* prev4 = (float4*)prev_s;

    // wpack[rp][dd] = pack(row 2rp, row 2rp+1) at dim dd*32+lane.
    // rows 0-3 = Wa[j0..j0+3], rows 4-7 = Wd[j0..j0+3]; pairs within same matrix.
    unsigned long long wpack[4][16];
    #pragma unroll
    for (int rp = 0; rp < 4; rp++) {
        const float* W = (rp < 2) ? Wa : Wd;
        const int rr = j0 + (rp & 1) * 2;
        #pragma unroll
        for (int dd = 0; dd < 16; dd++) {
            float wlo = W[(long)rr * 1024 + (dd << 5) + lane];
            float whi = W[(long)(rr + 1) * 1024 + (dd << 5) + lane];
            PACK2(wpack[rp][dd], wlo, whi);
        }
    }

    for (int t = 0; t < TT; t++) {
        float bt_v = 0.f, pa_v = 0.f, pd_v = 0.f;
        if (tid < 64) {
            long off = ((long)eb * TT + t) * DDIM + j0 + er;
            bt_v = bin[off]; pa_v = pa[off]; pd_v = pd[off];
        }

        // poll-load state slot t&3 (self-validating), stage into smem
        {
            const float4* sl = (const float4*)g_prev[t & 3];
            float4 v[8];
            #pragma unroll
            for (int i = 0; i < 8; i++) v[i] = __ldcv(sl + tid + i * 256);
            unsigned pend = 0xFFu;
            while (pend) {
                unsigned np = 0;
                #pragma unroll
                for (int i = 0; i < 8; i++)
                    if (pend & (1u << i)) {
                        if (v[i].x > -0.5f && v[i].y > -0.5f &&
                            v[i].z > -0.5f && v[i].w > -0.5f)
                            prev4[tid + i * 256] = v[i];
                        else np |= 1u << i;
                    }
                pend = np;
                if (pend) {
                    #pragma unroll
                    for (int i = 0; i < 8; i++)
                        if (pend & (1u << i)) v[i] = __ldcv(sl + tid + i * 256);
                }
            }
        }
        // safe now to re-poison our outputs in slot (t-2): every CTA consumed it
        if (t >= 2 && tid < 64)
            __stcg(&g_prev[(t - 2) & 3][eb * 512 + j0 + er], -1.f);
        __syncthreads();   // bar1: staging complete

        float pcur = (tid < 64) ? prev_s[eb * 512 + j0 + er] : 0.f;

        unsigned long long acc2[4][2];
        #pragma unroll
        for (int rp = 0; rp < 4; rp++) { acc2[rp][0] = 0ull; acc2[rp][1] = 0ull; }

        #pragma unroll
        for (int dd = 0; dd < 16; dd++) {
            const int d = (dd << 5) + lane;
            float p0 = prev_s[b0 * 512 + d];
            float p1 = prev_s[b0 * 512 + 512 + d];
            unsigned long long pd0, pd1;
            DUP2(pd0, p0); DUP2(pd1, p1);
            #pragma unroll
            for (int rp = 0; rp < 4; rp++) {
                FMA2(acc2[rp][0], wpack[rp][dd], pd0);
                FMA2(acc2[rp][1], wpack[rp][dd], pd1);
            }
        }
        float accs[8][2];
        #pragma unroll
        for (int rp = 0; rp < 4; rp++) {
            UNPACK2(accs[2*rp][0],   accs[2*rp+1][0],   acc2[rp][0]);
            UNPACK2(accs[2*rp][1],   accs[2*rp+1][1],   acc2[rp][1]);
        }
        #pragma unroll
        for (int r = 0; r < 8; r++)
            #pragma unroll
            for (int bI = 0; bI < 2; bI++) {
                float v = accs[r][bI];
                #pragma unroll
                for (int o = 16; o; o >>= 1) v += __shfl_xor_sync(0xffffffffu, v, o);
                accs[r][bI] = v;
            }
        if (lane == 0) {
            #pragma unroll
            for (int r = 0; r < 8; r++) {
                dot_s[r * 16 + b0]     = accs[r][0];
                dot_s[r * 16 + b0 + 1] = accs[r][1];
            }
        }
        __syncthreads();   // bar2: dot_s ready; also fences prev_s reuse

        if (tid < 64) {
            float alpha = tanhf(dot_s[er * 16 + eb] + pa_v);
            float delta = tanhf(dot_s[(4 + er) * 16 + eb] + pd_v);
            float x = alpha * bt_v + (1.f - alpha * delta) * pcur;
            float e = 1.f / (1.f + expf(-x));
            __stcg(&g_prev[(t + 1) & 3][eb * 512 + j0 + er], e);
            ema[((long)eb * TT + t) * DDIM + j0 + er] = e;
        }
        // no trailing bar: next poll is per-thread; prev_s writes gated by bar2,
        // next dot_s writes gated by next bar1.
    }
}

extern "C" void kernel_launch(void* const* d_in, const int* in_sizes, int n_in,
                              void* d_out, int out_size) {
    const float* b    = (const float*)d_in[0];
    const float* Wq   = (const float*)d_in[1];
    const float* bq   = (const float*)d_in[2];
    const float* Wk   = (const float*)d_in[3];
    const float* bk   = (const float*)d_in[4];
    const float* Wv   = (const float*)d_in[5];
    const float* bv   = (const float*)d_in[6];
    const float* Wa   = (const float*)d_in[7];
    const float* ba   = (const float*)d_in[8];
    const float* Wd   = (const float*)d_in[9];
    const float* bd   = (const float*)d_in[10];
    const float* Wout = (const float*)d_in[11];
    const float* bout = (const float*)d_in[12];
    const float* W_f  = (const float*)d_in[13];
    const float* b_f  = (const float*)d_in[14];
    const float* W_ec = (const float*)d_in[15];
    const float* W_zc = (const float*)d_in[16];
    const float* b_C  = (const float*)d_in[17];
    const float* W_i  = (const float*)d_in[18];
    const float* b_i  = (const float*)d_in[19];
    const float* W_o  = (const float*)d_in[20];
    const float* b_o  = (const float*)d_in[21];
    float* out = (float*)d_out;

    float* S = nullptr;
    cudaGetSymbolAddress((void**)&S, g_scratch);
    float* pre_a  = S + 0 * PER;
    float* pre_d  = S + 1 * PER;
    float* ema    = S + 2 * PER;
    float* bema   = S + 3 * PER;
    float* q      = S + 4 * PER;
    float* kmat   = S + 5 * PER;
    float* v      = S + 6 * PER;
    float* vT     = S + 7 * PER;
    float* z      = S + 8 * PER;
    float* zf     = S + 9 * PER;
    float* tmpc   = S + 10 * PER;
    float* zc     = S + 11 * PER;
    float* bh     = S + 12 * PER;
    float* scores = S + 13 * PER;
    float* wT1    = scores + 16777216L;
    float* wT2    = wT1 + 262144L;

    cudaFuncSetAttribute(tgemm<0>, cudaFuncAttributeMaxDynamicSharedMemorySize, GSMEM);
    cudaFuncSetAttribute(tgemm<1>, cudaFuncAttributeMaxDynamicSharedMemorySize, GSMEM);
    cudaFuncSetAttribute(tgemm<2>, cudaFuncAttributeMaxDynamicSharedMemorySize, GSMEM);
    cudaFuncSetAttribute(tgemm<3>, cudaFuncAttributeMaxDynamicSharedMemorySize, GSMEM);
    cudaFuncSetAttribute(tgemm<4>, cudaFuncAttributeMaxDynamicSharedMemorySize, GSMEM);
    cudaFuncSetAttribute(tgemm<5>, cudaFuncAttributeMaxDynamicSharedMemorySize, GSMEM);

    const dim3 blk(256);
    const dim3 gD(4, 128, 1);
    const long sBT = (long)TT * DDIM;
    const long sTT = (long)TT * TT;
    const float iscale = 1.f / sqrtf(512.f);

    init_k<<<128, 256>>>();
    transpose_k<<<dim3(16, 16, 1), dim3(32, 8)>>>(W_ec, wT1, 512, 512, 0, 0);
    transpose_k<<<dim3(16, 16, 1), dim3(32, 8)>>>(W_zc, wT2, 512, 512, 0, 0);

    tgemm<0><<<gD, blk, GSMEM>>>(b, Wa + 512, ba, nullptr, nullptr, pre_a, 512, 1024, 512, 0, 0, 0, 1.f);
    tgemm<0><<<gD, blk, GSMEM>>>(b, Wd + 512, bd, nullptr, nullptr, pre_d, 512, 1024, 512, 0, 0, 0, 1.f);

    ema_rec<<<128, 256>>>(b, pre_a, pre_d, Wa, Wd, ema);

    tgemm<1><<<gD, blk, GSMEM>>>(ema, Wout, bout, nullptr, nullptr, bema, 512, 512, 512, 0, 0, 0, 1.f);

    tgemm<0><<<gD, blk, GSMEM>>>(bema, Wq, bq, nullptr, nullptr, q,    512, 512, 512, 0, 0, 0, 1.f);
    tgemm<0><<<gD, blk, GSMEM>>>(bema, Wk, bk, nullptr, nullptr, kmat, 512, 512, 512, 0, 0, 0, 1.f);
    tgemm<0><<<gD, blk, GSMEM>>>(bema, Wv, bv, nullptr, nullptr, v,    512, 512, 512, 0, 0, 0, 1.f);

    tgemm<0><<<dim3(8, 8, 16), blk, GSMEM>>>(q, kmat, nullptr, nullptr, nullptr, scores,
                                             512, 512, 1024, sBT, sBT, sTT, iscale);
    softmax1024<<<BT, 256>>>(scores);

    transpose_k<<<dim3(16, 32, 16), dim3(32, 8)>>>(v, vT, 1024, 512, sBT, sBT);

    tgemm<0><<<dim3(4, 8, 16), blk, GSMEM>>>(scores, vT, nullptr, nullptr, nullptr, z,
                                             1024, 1024, 512, sTT, sBT, sBT, 1.f);

    tgemm<3><<<gD, blk, GSMEM>>>(bema, W_f, b_f, z, nullptr, zf, 512, 512, 512, 0, 0, 0, 1.f);
    tgemm<0><<<gD, blk, GSMEM>>>(bema, wT1, nullptr, nullptr, nullptr, tmpc, 512, 512, 512, 0, 0, 0, 1.f);
    tgemm<4><<<gD, blk, GSMEM>>>(zf, wT2, b_C, tmpc, nullptr, zc, 512, 512, 512, 0, 0, 0, 1.f);
    tgemm<5><<<gD, blk, GSMEM>>>(bema, W_i, b_i, zc, b, bh, 512, 512, 512, 0, 0, 0, 1.f);
    tgemm<2><<<gD, blk, GSMEM>>>(bh, W_o, b_o, nullptr, nullptr, out, 512, 512, 512, 0, 0, 0, 1.f);
}

// round 12
// speedup vs baseline: 1.7535x; 1.7535x over previous
#include <cuda_runtime.h>
#include <math.h>

#define BB 16
#define TT 1024
#define DDIM 512
#define BT (BB*TT)
#define PER ((long)BT*DDIM)

__device__ float g_scratch[13L*PER + 16777216L + 2L*262144L];
__device__ float g_prev[2][BB*DDIM];
__device__ int   g_cnt[TT + 1];

__device__ __forceinline__ float sigf(float x) { return 1.f / (1.f + expf(-x)); }
__device__ __forceinline__ float sigf_fast(float x) { return 1.f / (1.f + __expf(-x)); }
__device__ __forceinline__ float tanhf_fast(float x) {
    float e = __expf(2.f * x);            // inf-safe: x>>0 -> 1, x<<0 -> -1
    return 1.f - 2.f / (e + 1.f);
}
__device__ __forceinline__ int ldacq(const int* p) {
    int v; asm volatile("ld.acquire.gpu.global.b32 %0, [%1];" : "=r"(v) : "l"(p) : "memory");
    return v;
}
__device__ __forceinline__ void redrel(int* p) {
    asm volatile("red.release.gpu.global.add.s32 [%0], 1;" :: "l"(p) : "memory");
}
__device__ __forceinline__ void cp16(unsigned saddr, const void* g) {
    asm volatile("cp.async.ca.shared.global [%0], [%1], 16;" :: "r"(saddr), "l"(g));
}
#define FMA2(a,b,c) asm("fma.rn.f32x2 %0, %1, %2, %0;" : "+l"(a) : "l"(b), "l"(c))
#define DUP2(o,x)   asm("mov.b64 %0, {%1,%1};" : "=l"(o) : "r"(__float_as_uint(x)))
#define PACK2(o,lo,hi) asm("mov.b64 %0, {%1,%2};" : "=l"(o) : "r"(__float_as_uint(lo)), "r"(__float_as_uint(hi)))
#define UNPACK2(lo,hi,a) do { unsigned _l,_h; \
    asm("mov.b64 {%0,%1}, %2;" : "=r"(_l), "=r"(_h) : "l"(a)); \
    lo = __uint_as_float(_l); hi = __uint_as_float(_h); } while(0)

__global__ void init_k() {
    int tid = blockIdx.x * blockDim.x + threadIdx.x;
    if (tid < BB*DDIM) g_prev[0][tid] = 0.f;
    if (tid < TT + 1)  g_cnt[tid] = 0;
}

// in [Z,R,C] -> out [Z,C,R]
__global__ void transpose_k(const float* __restrict__ in, float* __restrict__ out,
                            int R, int C, long sIn, long sOut) {
    __shared__ float tile[32][33];
    const float* ib = in  + (long)blockIdx.z * sIn;
    float*       ob = out + (long)blockIdx.z * sOut;
    int c0 = blockIdx.x * 32, r0 = blockIdx.y * 32;
    for (int i = threadIdx.y; i < 32; i += 8)
        tile[i][threadIdx.x] = ib[(long)(r0 + i) * C + c0 + threadIdx.x];
    __syncthreads();
    for (int i = threadIdx.y; i < 32; i += 8)
        ob[(long)(c0 + i) * R + r0 + threadIdx.x] = tile[threadIdx.x][i];
}

__global__ void softmax1024(float* __restrict__ data) {
    __shared__ float red[8];
    int tid = threadIdx.x;
    float4* p = ((float4*)data) + ((long)blockIdx.x << 8);
    float4 v = p[tid];
    float m = fmaxf(fmaxf(v.x, v.y), fmaxf(v.z, v.w));
    #pragma unroll
    for (int o = 16; o; o >>= 1) m = fmaxf(m, __shfl_xor_sync(0xffffffffu, m, o));
    if ((tid & 31) == 0) red[tid >> 5] = m;
    __syncthreads();
    m = red[0];
    #pragma unroll
    for (int i = 1; i < 8; i++) m = fmaxf(m, red[i]);
    v.x = __expf(v.x - m); v.y = __expf(v.y - m);
    v.z = __expf(v.z - m); v.w = __expf(v.w - m);
    float s = v.x + v.y + v.z + v.w;
    #pragma unroll
    for (int o = 16; o; o >>= 1) s += __shfl_xor_sync(0xffffffffu, s, o);
    __syncthreads();
    if ((tid & 31) == 0) red[tid >> 5] = s;
    __syncthreads();
    s = red[0];
    #pragma unroll
    for (int i = 1; i < 8; i++) s += red[i];
    float inv = 1.f / s;
    v.x *= inv; v.y *= inv; v.z *= inv; v.w *= inv;
    p[tid] = v;
}

// ---------------------------------------------------------------------------
// tf32 tensor-core NT GEMM, cp.async 3-stage pipeline (proven; unchanged).
// ---------------------------------------------------------------------------
#define TSTRIDE 20
#define TSLOT (128 * TSTRIDE)
#define GSMEM (6 * TSLOT * 4)

template<int EPI>
__global__ __launch_bounds__(256)
void tgemm(const float* __restrict__ A, const float* __restrict__ Bw,
           const float* __restrict__ bias,
           const float* __restrict__ aux1, const float* __restrict__ aux2,
           float* __restrict__ C,
           int K, int ldb, int N, long sA, long sB, long sC, float scale)
{
    extern __shared__ float smem[];
    float* AsBase = smem;
    float* BsBase = smem + 3 * TSLOT;
    const int tid  = threadIdx.x;
    const int lane = tid & 31, warp = tid >> 5;
    const int wm = warp >> 2, wn = warp & 3;
    const int g = lane >> 2, t = lane & 3;
    const float* Ab = A  + (long)blockIdx.z * sA + (long)blockIdx.y * 128 * K;
    const float* Bb = Bw + (long)blockIdx.z * sB + (long)blockIdx.x * 128 * ldb;
    const int lr = tid >> 2, lc = (tid & 3) << 2;

    float acc[4][4][4];
    #pragma unroll
    for (int i = 0; i < 4; i++)
        #pragma unroll
        for (int j = 0; j < 4; j++)
            #pragma unroll
            for (int q = 0; q < 4; q++) acc[i][j][q] = 0.f;

    auto ISSUE = [&](int s, int kt) {
        float* As = AsBase + s * TSLOT;
        float* Bs = BsBase + s * TSLOT;
        cp16((unsigned)__cvta_generic_to_shared(&As[lr * TSTRIDE + lc]),
             &Ab[(long)lr * K + kt + lc]);
        cp16((unsigned)__cvta_generic_to_shared(&As[(lr + 64) * TSTRIDE + lc]),
             &Ab[(long)(lr + 64) * K + kt + lc]);
        cp16((unsigned)__cvta_generic_to_shared(&Bs[lr * TSTRIDE + lc]),
             &Bb[(long)lr * ldb + kt + lc]);
        cp16((unsigned)__cvta_generic_to_shared(&Bs[(lr + 64) * TSTRIDE + lc]),
             &Bb[(long)(lr + 64) * ldb + kt + lc]);
        asm volatile("cp.async.commit_group;" ::: "memory");
    };

    auto MM = [&](int s) {
        const float* As = AsBase + s * TSLOT;
        const float* Bs = BsBase + s * TSLOT;
        #pragma unroll
        for (int c = 0; c < 2; c++) {
            const int k0 = c * 8 + t;
            unsigned af[4][4], bf[4][2];
            #pragma unroll
            for (int i = 0; i < 4; i++) {
                const int m = wm * 64 + i * 16 + g;
                af[i][0] = __float_as_uint(As[m * TSTRIDE + k0]);
                af[i][1] = __float_as_uint(As[(m + 8) * TSTRIDE + k0]);
                af[i][2] = __float_as_uint(As[m * TSTRIDE + k0 + 4]);
                af[i][3] = __float_as_uint(As[(m + 8) * TSTRIDE + k0 + 4]);
            }
            #pragma unroll
            for (int j = 0; j < 4; j++) {
                const int n = wn * 32 + j * 8 + g;
                bf[j][0] = __float_as_uint(Bs[n * TSTRIDE + k0]);
                bf[j][1] = __float_as_uint(Bs[n * TSTRIDE + k0 + 4]);
            }
            #pragma unroll
            for (int i = 0; i < 4; i++)
                #pragma unroll
                for (int j = 0; j < 4; j++)
                    asm volatile(
                        "mma.sync.aligned.m16n8k8.row.col.f32.tf32.tf32.f32 "
                        "{%0,%1,%2,%3}, {%4,%5,%6,%7}, {%8,%9}, {%0,%1,%2,%3};\n"
                        : "+f"(acc[i][j][0]), "+f"(acc[i][j][1]),
                          "+f"(acc[i][j][2]), "+f"(acc[i][j][3])
                        : "r"(af[i][0]), "r"(af[i][1]), "r"(af[i][2]), "r"(af[i][3]),
                          "r"(bf[j][0]), "r"(bf[j][1]));
        }
    };

    const int nt = K >> 4;
    ISSUE(0, 0);
    ISSUE(1, 16);
    for (int tt = 0; tt < nt; tt++) {
        if (tt < nt - 1)
            asm volatile("cp.async.wait_group 1;" ::: "memory");
        else
            asm volatile("cp.async.wait_group 0;" ::: "memory");
        __syncthreads();
        MM(tt % 3);
        if (tt + 2 < nt) ISSUE((tt + 2) % 3, (tt + 2) * 16);
    }

    const int gn_base = blockIdx.x * 128 + wn * 32;
    #pragma unroll
    for (int i = 0; i < 4; i++) {
        const long m = (long)blockIdx.y * 128 + wm * 64 + i * 16 + g;
        #pragma unroll
        for (int j = 0; j < 4; j++) {
            const int n0 = gn_base + j * 8 + 2 * t;
            const float b0 = bias ? bias[n0]     : 0.f;
            const float b1 = bias ? bias[n0 + 1] : 0.f;
            const long i0 = (long)blockIdx.z * sC + m * N + n0;
            const long i2 = i0 + 8L * N;
            float x[4] = { acc[i][j][0] * scale + b0, acc[i][j][1] * scale + b1,
                           acc[i][j][2] * scale + b0, acc[i][j][3] * scale + b1 };
            const long idx[4] = { i0, i0 + 1, i2, i2 + 1 };
            float o[4];
            #pragma unroll
            for (int q = 0; q < 4; q++) {
                float xv = x[q];
                if (EPI == 0)      o[q] = xv;
                else if (EPI == 1) o[q] = xv * sigf(xv);
                else if (EPI == 2) o[q] = sigf(xv);
                else if (EPI == 3) o[q] = sigf(xv) * aux1[idx[q]];
                else if (EPI == 4) { float y = xv + aux1[idx[q]]; o[q] = y * sigf(y); }
                else { float s_ = sigf(xv); o[q] = s_ * aux1[idx[q]] + (1.f - s_) * aux2[idx[q]]; }
            }
            float2 w0 = { o[0], o[1] }, w1 = { o[2], o[3] };
            *(float2*)&C[i0] = w0;
            *(float2*)&C[i2] = w1;
        }
    }
}

// ---------------------------------------------------------------------------
// EMA recurrence: 128 CTAs x 256 thr. R9's proven flag barrier + staging,
// R11's verified f32x2 packed dot core, __expf-based tanh/sigmoid epilogue.
// Warp w owns batches {2w,2w+1}, all 8 rows (4 Wa + 4 Wd) via packed pairs.
// ---------------------------------------------------------------------------
__global__ __launch_bounds__(256, 1)
void ema_rec(const float* __restrict__ bin, const float* __restrict__ pa,
             const float* __restrict__ pd, const float* __restrict__ Wa,
             const float* __restrict__ Wd, float* __restrict__ ema)
{
    __shared__ float prev_s[16 * 512];
    __shared__ float dot_s[8 * 16];
    const int tid  = threadIdx.x;
    const int lane = tid & 31, warp = tid >> 5;
    const int j0 = blockIdx.x * 4;
    const int b0 = warp * 2;
    const int er = tid >> 4, eb = tid & 15;
    float4* prev4 = (float4*)prev_s;

    // wpack[rp][dd]: rp 0-1 = Wa row pairs (j0,j0+1),(j0+2,j0+3); rp 2-3 = Wd.
    unsigned long long wpack[4][16];
    #pragma unroll
    for (int rp = 0; rp < 4; rp++) {
        const float* W = (rp < 2) ? Wa : Wd;
        const int rr = j0 + (rp & 1) * 2;
        #pragma unroll
        for (int dd = 0; dd < 16; dd++) {
            float wlo = W[(long)rr * 1024 + (dd << 5) + lane];
            float whi = W[(long)(rr + 1) * 1024 + (dd << 5) + lane];
            PACK2(wpack[rp][dd], wlo, whi);
        }
    }

    for (int t = 0; t < TT; t++) {
        float bt_v = 0.f, pa_v = 0.f, pd_v = 0.f;
        if (tid < 64) {
            long off = ((long)eb * TT + t) * DDIM + j0 + er;
            bt_v = bin[off]; pa_v = pa[off]; pd_v = pd[off];
        }
        if (t) {
            if (tid == 0) { while (ldacq(&g_cnt[t]) < 128) { } }
            __syncthreads();
        }
        const float4* pg = (const float4*)g_prev[t & 1];
        #pragma unroll
        for (int i = 0; i < 8; i++)
            prev4[tid + i * 256] = __ldcv(pg + tid + i * 256);
        __syncthreads();

        float pcur = (tid < 64) ? prev_s[eb * 512 + j0 + er] : 0.f;

        unsigned long long acc2[4][2];
        #pragma unroll
        for (int rp = 0; rp < 4; rp++) { acc2[rp][0] = 0ull; acc2[rp][1] = 0ull; }

        #pragma unroll
        for (int dd = 0; dd < 16; dd++) {
            const int d = (dd << 5) + lane;
            float p0 = prev_s[b0 * 512 + d];
            float p1 = prev_s[b0 * 512 + 512 + d];
            unsigned long long pd0, pd1;
            DUP2(pd0, p0); DUP2(pd1, p1);
            #pragma unroll
            for (int rp = 0; rp < 4; rp++) {
                FMA2(acc2[rp][0], wpack[rp][dd], pd0);
                FMA2(acc2[rp][1], wpack[rp][dd], pd1);
            }
        }
        float accs[8][2];
        #pragma unroll
        for (int rp = 0; rp < 4; rp++) {
            UNPACK2(accs[2*rp][0], accs[2*rp+1][0], acc2[rp][0]);
            UNPACK2(accs[2*rp][1], accs[2*rp+1][1], acc2[rp][1]);
        }
        #pragma unroll
        for (int r = 0; r < 8; r++)
            #pragma unroll
            for (int bI = 0; bI < 2; bI++) {
                float v = accs[r][bI];
                #pragma unroll
                for (int o = 16; o; o >>= 1) v += __shfl_xor_sync(0xffffffffu, v, o);
                accs[r][bI] = v;
            }
        if (lane == 0) {
            #pragma unroll
            for (int r = 0; r < 8; r++) {
                dot_s[r * 16 + b0]     = accs[r][0];
                dot_s[r * 16 + b0 + 1] = accs[r][1];
            }
        }
        __syncthreads();

        if (tid < 64) {
            float alpha = tanhf_fast(dot_s[er * 16 + eb] + pa_v);
            float delta = tanhf_fast(dot_s[(4 + er) * 16 + eb] + pd_v);
            float x = alpha * bt_v + (1.f - alpha * delta) * pcur;
            float e = sigf_fast(x);
            g_prev[(t + 1) & 1][eb * 512 + j0 + er] = e;
            ema[((long)eb * TT + t) * DDIM + j0 + er] = e;
        }
        __syncthreads();
        if (tid == 0) redrel(&g_cnt[t + 1]);
    }
}

extern "C" void kernel_launch(void* const* d_in, const int* in_sizes, int n_in,
                              void* d_out, int out_size) {
    const float* b    = (const float*)d_in[0];
    const float* Wq   = (const float*)d_in[1];
    const float* bq   = (const float*)d_in[2];
    const float* Wk   = (const float*)d_in[3];
    const float* bk   = (const float*)d_in[4];
    const float* Wv   = (const float*)d_in[5];
    const float* bv   = (const float*)d_in[6];
    const float* Wa   = (const float*)d_in[7];
    const float* ba   = (const float*)d_in[8];
    const float* Wd   = (const float*)d_in[9];
    const float* bd   = (const float*)d_in[10];
    const float* Wout = (const float*)d_in[11];
    const float* bout = (const float*)d_in[12];
    const float* W_f  = (const float*)d_in[13];
    const float* b_f  = (const float*)d_in[14];
    const float* W_ec = (const float*)d_in[15];
    const float* W_zc = (const float*)d_in[16];
    const float* b_C  = (const float*)d_in[17];
    const float* W_i  = (const float*)d_in[18];
    const float* b_i  = (const float*)d_in[19];
    const float* W_o  = (const float*)d_in[20];
    const float* b_o  = (const float*)d_in[21];
    float* out = (float*)d_out;

    float* S = nullptr;
    cudaGetSymbolAddress((void**)&S, g_scratch);
    float* pre_a  = S + 0 * PER;
    float* pre_d  = S + 1 * PER;
    float* ema    = S + 2 * PER;
    float* bema   = S + 3 * PER;
    float* q      = S + 4 * PER;
    float* kmat   = S + 5 * PER;
    float* v      = S + 6 * PER;
    float* vT     = S + 7 * PER;
    float* z      = S + 8 * PER;
    float* zf     = S + 9 * PER;
    float* tmpc   = S + 10 * PER;
    float* zc     = S + 11 * PER;
    float* bh     = S + 12 * PER;
    float* scores = S + 13 * PER;
    float* wT1    = scores + 16777216L;
    float* wT2    = wT1 + 262144L;

    cudaFuncSetAttribute(tgemm<0>, cudaFuncAttributeMaxDynamicSharedMemorySize, GSMEM);
    cudaFuncSetAttribute(tgemm<1>, cudaFuncAttributeMaxDynamicSharedMemorySize, GSMEM);
    cudaFuncSetAttribute(tgemm<2>, cudaFuncAttributeMaxDynamicSharedMemorySize, GSMEM);
    cudaFuncSetAttribute(tgemm<3>, cudaFuncAttributeMaxDynamicSharedMemorySize, GSMEM);
    cudaFuncSetAttribute(tgemm<4>, cudaFuncAttributeMaxDynamicSharedMemorySize, GSMEM);
    cudaFuncSetAttribute(tgemm<5>, cudaFuncAttributeMaxDynamicSharedMemorySize, GSMEM);

    const dim3 blk(256);
    const dim3 gD(4, 128, 1);
    const long sBT = (long)TT * DDIM;
    const long sTT = (long)TT * TT;
    const float iscale = 1.f / sqrtf(512.f);

    init_k<<<32, 256>>>();
    transpose_k<<<dim3(16, 16, 1), dim3(32, 8)>>>(W_ec, wT1, 512, 512, 0, 0);
    transpose_k<<<dim3(16, 16, 1), dim3(32, 8)>>>(W_zc, wT2, 512, 512, 0, 0);

    tgemm<0><<<gD, blk, GSMEM>>>(b, Wa + 512, ba, nullptr, nullptr, pre_a, 512, 1024, 512, 0, 0, 0, 1.f);
    tgemm<0><<<gD, blk, GSMEM>>>(b, Wd + 512, bd, nullptr, nullptr, pre_d, 512, 1024, 512, 0, 0, 0, 1.f);

    ema_rec<<<128, 256>>>(b, pre_a, pre_d, Wa, Wd, ema);

    tgemm<1><<<gD, blk, GSMEM>>>(ema, Wout, bout, nullptr, nullptr, bema, 512, 512, 512, 0, 0, 0, 1.f);

    tgemm<0><<<gD, blk, GSMEM>>>(bema, Wq, bq, nullptr, nullptr, q,    512, 512, 512, 0, 0, 0, 1.f);
    tgemm<0><<<gD, blk, GSMEM>>>(bema, Wk, bk, nullptr, nullptr, kmat, 512, 512, 512, 0, 0, 0, 1.f);
    tgemm<0><<<gD, blk, GSMEM>>>(bema, Wv, bv, nullptr, nullptr, v,    512, 512, 512, 0, 0, 0, 1.f);

    tgemm<0><<<dim3(8, 8, 16), blk, GSMEM>>>(q, kmat, nullptr, nullptr, nullptr, scores,
                                             512, 512, 1024, sBT, sBT, sTT, iscale);
    softmax1024<<<BT, 256>>>(scores);

    transpose_k<<<dim3(16, 32, 16), dim3(32, 8)>>>(v, vT, 1024, 512, sBT, sBT);

    tgemm<0><<<dim3(4, 8, 16), blk, GSMEM>>>(scores, vT, nullptr, nullptr, nullptr, z,
                                             1024, 1024, 512, sTT, sBT, sBT, 1.f);

    tgemm<3><<<gD, blk, GSMEM>>>(bema, W_f, b_f, z, nullptr, zf, 512, 512, 512, 0, 0, 0, 1.f);
    tgemm<0><<<gD, blk, GSMEM>>>(bema, wT1, nullptr, nullptr, nullptr, tmpc, 512, 512, 512, 0, 0, 0, 1.f);
    tgemm<4><<<gD, blk, GSMEM>>>(zf, wT2, b_C, tmpc, nullptr, zc, 512, 512, 512, 0, 0, 0, 1.f);
    tgemm<5><<<gD, blk, GSMEM>>>(bema, W_i, b_i, zc, b, bh, 512, 512, 512, 0, 0, 0, 1.f);
    tgemm<2><<<gD, blk, GSMEM>>>(bh, W_o, b_o, nullptr, nullptr, out, 512, 512, 512, 0, 0, 0, 1.f);
}

// round 13
// speedup vs baseline: 1.9440x; 1.1086x over previous
#include <cuda_runtime.h>
#include <math.h>

#define BB 16
#define TT 1024
#define DDIM 512
#define BT (BB*TT)
#define PER ((long)BT*DDIM)

__device__ float g_scratch[13L*PER + 16777216L + 2L*262144L];
__device__ float g_prev[2][BB*DDIM];
__device__ int   g_cnt2[8][TT + 1];    // per-group step counters

__device__ __forceinline__ float sigf(float x) { return 1.f / (1.f + expf(-x)); }
__device__ __forceinline__ float sigf_fast(float x) { return 1.f / (1.f + __expf(-x)); }
__device__ __forceinline__ float tanhf_fast(float x) {
    float e = __expf(2.f * x);
    return 1.f - 2.f / (e + 1.f);
}
__device__ __forceinline__ int ldacq(const int* p) {
    int v; asm volatile("ld.acquire.gpu.global.b32 %0, [%1];" : "=r"(v) : "l"(p) : "memory");
    return v;
}
__device__ __forceinline__ void redrel(int* p) {
    asm volatile("red.release.gpu.global.add.s32 [%0], 1;" :: "l"(p) : "memory");
}
__device__ __forceinline__ void cp16(unsigned saddr, const void* g) {
    asm volatile("cp.async.ca.shared.global [%0], [%1], 16;" :: "r"(saddr), "l"(g));
}
#define FMA2(a,b,c) asm("fma.rn.f32x2 %0, %1, %2, %0;" : "+l"(a) : "l"(b), "l"(c))
#define DUP2(o,x)   asm("mov.b64 %0, {%1,%1};" : "=l"(o) : "r"(__float_as_uint(x)))
#define PACK2(o,lo,hi) asm("mov.b64 %0, {%1,%2};" : "=l"(o) : "r"(__float_as_uint(lo)), "r"(__float_as_uint(hi)))
#define UNPACK2(lo,hi,a) do { unsigned _l,_h; \
    asm("mov.b64 {%0,%1}, %2;" : "=r"(_l), "=r"(_h) : "l"(a)); \
    lo = __uint_as_float(_l); hi = __uint_as_float(_h); } while(0)

__global__ void init_k() {
    int tid = blockIdx.x * blockDim.x + threadIdx.x;
    if (tid < BB*DDIM) g_prev[0][tid] = 0.f;
    if (tid < 8 * (TT + 1)) ((int*)g_cnt2)[tid] = 0;
}

// in [Z,R,C] -> out [Z,C,R]
__global__ void transpose_k(const float* __restrict__ in, float* __restrict__ out,
                            int R, int C, long sIn, long sOut) {
    __shared__ float tile[32][33];
    const float* ib = in  + (long)blockIdx.z * sIn;
    float*       ob = out + (long)blockIdx.z * sOut;
    int c0 = blockIdx.x * 32, r0 = blockIdx.y * 32;
    for (int i = threadIdx.y; i < 32; i += 8)
        tile[i][threadIdx.x] = ib[(long)(r0 + i) * C + c0 + threadIdx.x];
    __syncthreads();
    for (int i = threadIdx.y; i < 32; i += 8)
        ob[(long)(c0 + i) * R + r0 + threadIdx.x] = tile[threadIdx.x][i];
}

__global__ void softmax1024(float* __restrict__ data) {
    __shared__ float red[8];
    int tid = threadIdx.x;
    float4* p = ((float4*)data) + ((long)blockIdx.x << 8);
    float4 v = p[tid];
    float m = fmaxf(fmaxf(v.x, v.y), fmaxf(v.z, v.w));
    #pragma unroll
    for (int o = 16; o; o >>= 1) m = fmaxf(m, __shfl_xor_sync(0xffffffffu, m, o));
    if ((tid & 31) == 0) red[tid >> 5] = m;
    __syncthreads();
    m = red[0];
    #pragma unroll
    for (int i = 1; i < 8; i++) m = fmaxf(m, red[i]);
    v.x = __expf(v.x - m); v.y = __expf(v.y - m);
    v.z = __expf(v.z - m); v.w = __expf(v.w - m);
    float s = v.x + v.y + v.z + v.w;
    #pragma unroll
    for (int o = 16; o; o >>= 1) s += __shfl_xor_sync(0xffffffffu, s, o);
    __syncthreads();
    if ((tid & 31) == 0) red[tid >> 5] = s;
    __syncthreads();
    s = red[0];
    #pragma unroll
    for (int i = 1; i < 8; i++) s += red[i];
    float inv = 1.f / s;
    v.x *= inv; v.y *= inv; v.z *= inv; v.w *= inv;
    p[tid] = v;
}

// ---------------------------------------------------------------------------
// tf32 tensor-core NT GEMM, cp.async 3-stage pipeline (proven; unchanged).
// ---------------------------------------------------------------------------
#define TSTRIDE 20
#define TSLOT (128 * TSTRIDE)
#define GSMEM (6 * TSLOT * 4)

template<int EPI>
__global__ __launch_bounds__(256)
void tgemm(const float* __restrict__ A, const float* __restrict__ Bw,
           const float* __restrict__ bias,
           const float* __restrict__ aux1, const float* __restrict__ aux2,
           float* __restrict__ C,
           int K, int ldb, int N, long sA, long sB, long sC, float scale)
{
    extern __shared__ float smem[];
    float* AsBase = smem;
    float* BsBase = smem + 3 * TSLOT;
    const int tid  = threadIdx.x;
    const int lane = tid & 31, warp = tid >> 5;
    const int wm = warp >> 2, wn = warp & 3;
    const int g = lane >> 2, t = lane & 3;
    const float* Ab = A  + (long)blockIdx.z * sA + (long)blockIdx.y * 128 * K;
    const float* Bb = Bw + (long)blockIdx.z * sB + (long)blockIdx.x * 128 * ldb;
    const int lr = tid >> 2, lc = (tid & 3) << 2;

    float acc[4][4][4];
    #pragma unroll
    for (int i = 0; i < 4; i++)
        #pragma unroll
        for (int j = 0; j < 4; j++)
            #pragma unroll
            for (int q = 0; q < 4; q++) acc[i][j][q] = 0.f;

    auto ISSUE = [&](int s, int kt) {
        float* As = AsBase + s * TSLOT;
        float* Bs = BsBase + s * TSLOT;
        cp16((unsigned)__cvta_generic_to_shared(&As[lr * TSTRIDE + lc]),
             &Ab[(long)lr * K + kt + lc]);
        cp16((unsigned)__cvta_generic_to_shared(&As[(lr + 64) * TSTRIDE + lc]),
             &Ab[(long)(lr + 64) * K + kt + lc]);
        cp16((unsigned)__cvta_generic_to_shared(&Bs[lr * TSTRIDE + lc]),
             &Bb[(long)lr * ldb + kt + lc]);
        cp16((unsigned)__cvta_generic_to_shared(&Bs[(lr + 64) * TSTRIDE + lc]),
             &Bb[(long)(lr + 64) * ldb + kt + lc]);
        asm volatile("cp.async.commit_group;" ::: "memory");
    };

    auto MM = [&](int s) {
        const float* As = AsBase + s * TSLOT;
        const float* Bs = BsBase + s * TSLOT;
        #pragma unroll
        for (int c = 0; c < 2; c++) {
            const int k0 = c * 8 + t;
            unsigned af[4][4], bf[4][2];
            #pragma unroll
            for (int i = 0; i < 4; i++) {
                const int m = wm * 64 + i * 16 + g;
                af[i][0] = __float_as_uint(As[m * TSTRIDE + k0]);
                af[i][1] = __float_as_uint(As[(m + 8) * TSTRIDE + k0]);
                af[i][2] = __float_as_uint(As[m * TSTRIDE + k0 + 4]);
                af[i][3] = __float_as_uint(As[(m + 8) * TSTRIDE + k0 + 4]);
            }
            #pragma unroll
            for (int j = 0; j < 4; j++) {
                const int n = wn * 32 + j * 8 + g;
                bf[j][0] = __float_as_uint(Bs[n * TSTRIDE + k0]);
                bf[j][1] = __float_as_uint(Bs[n * TSTRIDE + k0 + 4]);
            }
            #pragma unroll
            for (int i = 0; i < 4; i++)
                #pragma unroll
                for (int j = 0; j < 4; j++)
                    asm volatile(
                        "mma.sync.aligned.m16n8k8.row.col.f32.tf32.tf32.f32 "
                        "{%0,%1,%2,%3}, {%4,%5,%6,%7}, {%8,%9}, {%0,%1,%2,%3};\n"
                        : "+f"(acc[i][j][0]), "+f"(acc[i][j][1]),
                          "+f"(acc[i][j][2]), "+f"(acc[i][j][3])
                        : "r"(af[i][0]), "r"(af[i][1]), "r"(af[i][2]), "r"(af[i][3]),
                          "r"(bf[j][0]), "r"(bf[j][1]));
        }
    };

    const int nt = K >> 4;
    ISSUE(0, 0);
    ISSUE(1, 16);
    for (int tt = 0; tt < nt; tt++) {
        if (tt < nt - 1)
            asm volatile("cp.async.wait_group 1;" ::: "memory");
        else
            asm volatile("cp.async.wait_group 0;" ::: "memory");
        __syncthreads();
        MM(tt % 3);
        if (tt + 2 < nt) ISSUE((tt + 2) % 3, (tt + 2) * 16);
    }

    const int gn_base = blockIdx.x * 128 + wn * 32;
    #pragma unroll
    for (int i = 0; i < 4; i++) {
        const long m = (long)blockIdx.y * 128 + wm * 64 + i * 16 + g;
        #pragma unroll
        for (int j = 0; j < 4; j++) {
            const int n0 = gn_base + j * 8 + 2 * t;
            const float b0 = bias ? bias[n0]     : 0.f;
            const float b1 = bias ? bias[n0 + 1] : 0.f;
            const long i0 = (long)blockIdx.z * sC + m * N + n0;
            const long i2 = i0 + 8L * N;
            float x[4] = { acc[i][j][0] * scale + b0, acc[i][j][1] * scale + b1,
                           acc[i][j][2] * scale + b0, acc[i][j][3] * scale + b1 };
            const long idx[4] = { i0, i0 + 1, i2, i2 + 1 };
            float o[4];
            #pragma unroll
            for (int q = 0; q < 4; q++) {
                float xv = x[q];
                if (EPI == 0)      o[q] = xv;
                else if (EPI == 1) o[q] = xv * sigf(xv);
                else if (EPI == 2) o[q] = sigf(xv);
                else if (EPI == 3) o[q] = sigf(xv) * aux1[idx[q]];
                else if (EPI == 4) { float y = xv + aux1[idx[q]]; o[q] = y * sigf(y); }
                else { float s_ = sigf(xv); o[q] = s_ * aux1[idx[q]] + (1.f - s_) * aux2[idx[q]]; }
            }
            float2 w0 = { o[0], o[1] }, w1 = { o[2], o[3] };
            *(float2*)&C[i0] = w0;
            *(float2*)&C[i2] = w1;
        }
    }
}

// ---------------------------------------------------------------------------
// EMA recurrence — batch-grouped. Batches are independent, so CTAs are split
// into 8 groups of 16; group g owns batches {2g, 2g+1}. CTA (g, m) computes
// rows j0=32m..j0+31 of alpha AND delta for those 2 batches. Sync is only
// within the 16-CTA group (own counter array): 4KB state exchange per step.
// Warp w (0..7): matrix (w<4 ? Wa : Wd), rows j0+(w&3)*8 .. +8, both batches.
// Same release/acquire protocol and f32x2 dot core as the proven R12 kernel.
// ---------------------------------------------------------------------------
__global__ __launch_bounds__(256, 1)
void ema_rec(const float* __restrict__ bin, const float* __restrict__ pa,
             const float* __restrict__ pd, const float* __restrict__ Wa,
             const float* __restrict__ Wd, float* __restrict__ ema)
{
    __shared__ float prev_s[1024];     // [2 batches][512]
    __shared__ float dot_s[256];       // [2 mats][32 rows][2 batches]
    const int tid  = threadIdx.x;
    const int lane = tid & 31, warp = tid >> 5;
    const int grp   = blockIdx.x >> 4;          // 0..7
    const int j0    = (blockIdx.x & 15) * 32;   // row block
    const int bbase = grp * 2;
    const int er = tid & 31, ebI = tid >> 5;    // epilogue map (tid<64)
    float4* prev4 = (float4*)prev_s;
    int* cnt = g_cnt2[grp];

    // wpack[rp][dd] = pack(row rb+2rp, row rb+2rp+1) at dim dd*32+lane
    const float* Wsel = (warp < 4) ? Wa : Wd;
    const int rb = j0 + (warp & 3) * 8;
    unsigned long long wpack[4][16];
    #pragma unroll
    for (int rp = 0; rp < 4; rp++)
        #pragma unroll
        for (int dd = 0; dd < 16; dd++) {
            float wlo = Wsel[(long)(rb + 2*rp)     * 1024 + (dd << 5) + lane];
            float whi = Wsel[(long)(rb + 2*rp + 1) * 1024 + (dd << 5) + lane];
            PACK2(wpack[rp][dd], wlo, whi);
        }

    for (int t = 0; t < TT; t++) {
        float bt_v = 0.f, pa_v = 0.f, pd_v = 0.f;
        if (tid < 64) {
            long off = ((long)(bbase + ebI) * TT + t) * DDIM + j0 + er;
            bt_v = bin[off]; pa_v = pa[off]; pd_v = pd[off];
        }
        if (t) {
            if (tid == 0) { while (ldacq(&cnt[t]) < 16) { } }
            __syncthreads();
        }
        // stage 2 batches of state (contiguous 4KB, 1 float4/thread)
        const float4* pg = (const float4*)(g_prev[t & 1] + (long)bbase * 512);
        prev4[tid] = __ldcv(pg + tid);
        __syncthreads();

        float pcur = (tid < 64) ? prev_s[ebI * 512 + j0 + er] : 0.f;

        unsigned long long acc2[4][2];
        #pragma unroll
        for (int rp = 0; rp < 4; rp++) { acc2[rp][0] = 0ull; acc2[rp][1] = 0ull; }

        #pragma unroll
        for (int dd = 0; dd < 16; dd++) {
            const int d = (dd << 5) + lane;
            float p0 = prev_s[d];
            float p1 = prev_s[512 + d];
            unsigned long long q0, q1;
            DUP2(q0, p0); DUP2(q1, p1);
            #pragma unroll
            for (int rp = 0; rp < 4; rp++) {
                FMA2(acc2[rp][0], wpack[rp][dd], q0);
                FMA2(acc2[rp][1], wpack[rp][dd], q1);
            }
        }
        float accs[8][2];
        #pragma unroll
        for (int rp = 0; rp < 4; rp++) {
            UNPACK2(accs[2*rp][0], accs[2*rp+1][0], acc2[rp][0]);
            UNPACK2(accs[2*rp][1], accs[2*rp+1][1], acc2[rp][1]);
        }
        #pragma unroll
        for (int r = 0; r < 8; r++)
            #pragma unroll
            for (int bI = 0; bI < 2; bI++) {
                float v = accs[r][bI];
                #pragma unroll
                for (int o = 16; o; o >>= 1) v += __shfl_xor_sync(0xffffffffu, v, o);
                accs[r][bI] = v;
            }
        if (lane == 0) {
            const int base = (warp < 4) ? 0 : 128;
            const int rl = (warp & 3) * 8;
            #pragma unroll
            for (int r = 0; r < 8; r++) {
                dot_s[base + (rl + r) * 2 + 0] = accs[r][0];
                dot_s[base + (rl + r) * 2 + 1] = accs[r][1];
            }
        }
        __syncthreads();

        if (tid < 64) {
            float alpha = tanhf_fast(dot_s[er * 2 + ebI] + pa_v);
            float delta = tanhf_fast(dot_s[128 + er * 2 + ebI] + pd_v);
            float x = alpha * bt_v + (1.f - alpha * delta) * pcur;
            float e = sigf_fast(x);
            g_prev[(t + 1) & 1][(long)(bbase + ebI) * 512 + j0 + er] = e;
            ema[((long)(bbase + ebI) * TT + t) * DDIM + j0 + er] = e;
        }
        __syncthreads();
        if (tid == 0) redrel(&cnt[t + 1]);
    }
}

extern "C" void kernel_launch(void* const* d_in, const int* in_sizes, int n_in,
                              void* d_out, int out_size) {
    const float* b    = (const float*)d_in[0];
    const float* Wq   = (const float*)d_in[1];
    const float* bq   = (const float*)d_in[2];
    const float* Wk   = (const float*)d_in[3];
    const float* bk   = (const float*)d_in[4];
    const float* Wv   = (const float*)d_in[5];
    const float* bv   = (const float*)d_in[6];
    const float* Wa   = (const float*)d_in[7];
    const float* ba   = (const float*)d_in[8];
    const float* Wd   = (const float*)d_in[9];
    const float* bd   = (const float*)d_in[10];
    const float* Wout = (const float*)d_in[11];
    const float* bout = (const float*)d_in[12];
    const float* W_f  = (const float*)d_in[13];
    const float* b_f  = (const float*)d_in[14];
    const float* W_ec = (const float*)d_in[15];
    const float* W_zc = (const float*)d_in[16];
    const float* b_C  = (const float*)d_in[17];
    const float* W_i  = (const float*)d_in[18];
    const float* b_i  = (const float*)d_in[19];
    const float* W_o  = (const float*)d_in[20];
    const float* b_o  = (const float*)d_in[21];
    float* out = (float*)d_out;

    float* S = nullptr;
    cudaGetSymbolAddress((void**)&S, g_scratch);
    float* pre_a  = S + 0 * PER;
    float* pre_d  = S + 1 * PER;
    float* ema    = S + 2 * PER;
    float* bema   = S + 3 * PER;
    float* q      = S + 4 * PER;
    float* kmat   = S + 5 * PER;
    float* v      = S + 6 * PER;
    float* vT     = S + 7 * PER;
    float* z      = S + 8 * PER;
    float* zf     = S + 9 * PER;
    float* tmpc   = S + 10 * PER;
    float* zc     = S + 11 * PER;
    float* bh     = S + 12 * PER;
    float* scores = S + 13 * PER;
    float* wT1    = scores + 16777216L;
    float* wT2    = wT1 + 262144L;

    cudaFuncSetAttribute(tgemm<0>, cudaFuncAttributeMaxDynamicSharedMemorySize, GSMEM);
    cudaFuncSetAttribute(tgemm<1>, cudaFuncAttributeMaxDynamicSharedMemorySize, GSMEM);
    cudaFuncSetAttribute(tgemm<2>, cudaFuncAttributeMaxDynamicSharedMemorySize, GSMEM);
    cudaFuncSetAttribute(tgemm<3>, cudaFuncAttributeMaxDynamicSharedMemorySize, GSMEM);
    cudaFuncSetAttribute(tgemm<4>, cudaFuncAttributeMaxDynamicSharedMemorySize, GSMEM);
    cudaFuncSetAttribute(tgemm<5>, cudaFuncAttributeMaxDynamicSharedMemorySize, GSMEM);

    const dim3 blk(256);
    const dim3 gD(4, 128, 1);
    const long sBT = (long)TT * DDIM;
    const long sTT = (long)TT * TT;
    const float iscale = 1.f / sqrtf(512.f);

    init_k<<<64, 256>>>();
    transpose_k<<<dim3(16, 16, 1), dim3(32, 8)>>>(W_ec, wT1, 512, 512, 0, 0);
    transpose_k<<<dim3(16, 16, 1), dim3(32, 8)>>>(W_zc, wT2, 512, 512, 0, 0);

    tgemm<0><<<gD, blk, GSMEM>>>(b, Wa + 512, ba, nullptr, nullptr, pre_a, 512, 1024, 512, 0, 0, 0, 1.f);
    tgemm<0><<<gD, blk, GSMEM>>>(b, Wd + 512, bd, nullptr, nullptr, pre_d, 512, 1024, 512, 0, 0, 0, 1.f);

    ema_rec<<<128, 256>>>(b, pre_a, pre_d, Wa, Wd, ema);

    tgemm<1><<<gD, blk, GSMEM>>>(ema, Wout, bout, nullptr, nullptr, bema, 512, 512, 512, 0, 0, 0, 1.f);

    tgemm<0><<<gD, blk, GSMEM>>>(bema, Wq, bq, nullptr, nullptr, q,    512, 512, 512, 0, 0, 0, 1.f);
    tgemm<0><<<gD, blk, GSMEM>>>(bema, Wk, bk, nullptr, nullptr, kmat, 512, 512, 512, 0, 0, 0, 1.f);
    tgemm<0><<<gD, blk, GSMEM>>>(bema, Wv, bv, nullptr, nullptr, v,    512, 512, 512, 0, 0, 0, 1.f);

    tgemm<0><<<dim3(8, 8, 16), blk, GSMEM>>>(q, kmat, nullptr, nullptr, nullptr, scores,
                                             512, 512, 1024, sBT, sBT, sTT, iscale);
    softmax1024<<<BT, 256>>>(scores);

    transpose_k<<<dim3(16, 32, 16), dim3(32, 8)>>>(v, vT, 1024, 512, sBT, sBT);

    tgemm<0><<<dim3(4, 8, 16), blk, GSMEM>>>(scores, vT, nullptr, nullptr, nullptr, z,
                                             1024, 1024, 512, sTT, sBT, sBT, 1.f);

    tgemm<3><<<gD, blk, GSMEM>>>(bema, W_f, b_f, z, nullptr, zf, 512, 512, 512, 0, 0, 0, 1.f);
    tgemm<0><<<gD, blk, GSMEM>>>(bema, wT1, nullptr, nullptr, nullptr, tmpc, 512, 512, 512, 0, 0, 0, 1.f);
    tgemm<4><<<gD, blk, GSMEM>>>(zf, wT2, b_C, tmpc, nullptr, zc, 512, 512, 512, 0, 0, 0, 1.f);
    tgemm<5><<<gD, blk, GSMEM>>>(bema, W_i, b_i, zc, b, bh, 512, 512, 512, 0, 0, 0, 1.f);
    tgemm<2><<<gD, blk, GSMEM>>>(bh, W_o, b_o, nullptr, nullptr, out, 512, 512, 512, 0, 0, 0, 1.f);
}

// round 14
// speedup vs baseline: 2.1003x; 1.0804x over previous
#include <cuda_runtime.h>
#include <math.h>

#define BB 16
#define TT 1024
#define DDIM 512
#define BT (BB*TT)
#define PER ((long)BT*DDIM)

__device__ float g_scratch[13L*PER + 16777216L + 2L*262144L];
__device__ float g_prev[2][BB*DDIM];
__device__ int   g_cnt2[8][TT + 1];    // per-group step counters

__device__ __forceinline__ float sigf(float x) { return 1.f / (1.f + expf(-x)); }
__device__ __forceinline__ float sigf_fast(float x) { return 1.f / (1.f + __expf(-x)); }
__device__ __forceinline__ float tanhf_fast(float x) {
    float e = __expf(2.f * x);
    return 1.f - 2.f / (e + 1.f);
}
__device__ __forceinline__ int ldacq(const int* p) {
    int v; asm volatile("ld.acquire.gpu.global.b32 %0, [%1];" : "=r"(v) : "l"(p) : "memory");
    return v;
}
__device__ __forceinline__ void redrel(int* p) {
    asm volatile("red.release.gpu.global.add.s32 [%0], 1;" :: "l"(p) : "memory");
}
__device__ __forceinline__ void cp16(unsigned saddr, const void* g) {
    asm volatile("cp.async.ca.shared.global [%0], [%1], 16;" :: "r"(saddr), "l"(g));
}
#define FMA2(a,b,c) asm("fma.rn.f32x2 %0, %1, %2, %0;" : "+l"(a) : "l"(b), "l"(c))
#define DUP2(o,x)   asm("mov.b64 %0, {%1,%1};" : "=l"(o) : "r"(__float_as_uint(x)))
#define PACK2(o,lo,hi) asm("mov.b64 %0, {%1,%2};" : "=l"(o) : "r"(__float_as_uint(lo)), "r"(__float_as_uint(hi)))
#define UNPACK2(lo,hi,a) do { unsigned _l,_h; \
    asm("mov.b64 {%0,%1}, %2;" : "=r"(_l), "=r"(_h) : "l"(a)); \
    lo = __uint_as_float(_l); hi = __uint_as_float(_h); } while(0)

__global__ void init_k() {
    int tid = blockIdx.x * blockDim.x + threadIdx.x;
    if (tid < BB*DDIM) g_prev[0][tid] = 0.f;
    if (tid < 8 * (TT + 1)) ((int*)g_cnt2)[tid] = 0;
}

// in [Z,R,C] -> out [Z,C,R]
__global__ void transpose_k(const float* __restrict__ in, float* __restrict__ out,
                            int R, int C, long sIn, long sOut) {
    __shared__ float tile[32][33];
    const float* ib = in  + (long)blockIdx.z * sIn;
    float*       ob = out + (long)blockIdx.z * sOut;
    int c0 = blockIdx.x * 32, r0 = blockIdx.y * 32;
    for (int i = threadIdx.y; i < 32; i += 8)
        tile[i][threadIdx.x] = ib[(long)(r0 + i) * C + c0 + threadIdx.x];
    __syncthreads();
    for (int i = threadIdx.y; i < 32; i += 8)
        ob[(long)(c0 + i) * R + r0 + threadIdx.x] = tile[threadIdx.x][i];
}

__global__ void softmax1024(float* __restrict__ data) {
    __shared__ float red[8];
    int tid = threadIdx.x;
    float4* p = ((float4*)data) + ((long)blockIdx.x << 8);
    float4 v = p[tid];
    float m = fmaxf(fmaxf(v.x, v.y), fmaxf(v.z, v.w));
    #pragma unroll
    for (int o = 16; o; o >>= 1) m = fmaxf(m, __shfl_xor_sync(0xffffffffu, m, o));
    if ((tid & 31) == 0) red[tid >> 5] = m;
    __syncthreads();
    m = red[0];
    #pragma unroll
    for (int i = 1; i < 8; i++) m = fmaxf(m, red[i]);
    v.x = __expf(v.x - m); v.y = __expf(v.y - m);
    v.z = __expf(v.z - m); v.w = __expf(v.w - m);
    float s = v.x + v.y + v.z + v.w;
    #pragma unroll
    for (int o = 16; o; o >>= 1) s += __shfl_xor_sync(0xffffffffu, s, o);
    __syncthreads();
    if ((tid & 31) == 0) red[tid >> 5] = s;
    __syncthreads();
    s = red[0];
    #pragma unroll
    for (int i = 1; i < 8; i++) s += red[i];
    float inv = 1.f / s;
    v.x *= inv; v.y *= inv; v.z *= inv; v.w *= inv;
    p[tid] = v;
}

// ---------------------------------------------------------------------------
// tf32 tensor-core NT GEMM, cp.async 3-stage pipeline, K-chunk 32.
// smem tiles [128 m][32 k] stride 36 floats: fragment LDS conflict-free
// (bank = (36g+t) mod 32 = (4g+t) mod 32 covers all 32); rows 144B (16B-mult).
// ---------------------------------------------------------------------------
#define TSTRIDE 36
#define TSLOT (128 * TSTRIDE)
#define GSMEM (6 * TSLOT * 4)          // 110592 bytes

template<int EPI>
__global__ __launch_bounds__(256)
void tgemm(const float* __restrict__ A, const float* __restrict__ Bw,
           const float* __restrict__ bias,
           const float* __restrict__ aux1, const float* __restrict__ aux2,
           float* __restrict__ C,
           int K, int ldb, int N, long sA, long sB, long sC, float scale)
{
    extern __shared__ float smem[];
    float* AsBase = smem;
    float* BsBase = smem + 3 * TSLOT;
    const int tid  = threadIdx.x;
    const int lane = tid & 31, warp = tid >> 5;
    const int wm = warp >> 2, wn = warp & 3;
    const int g = lane >> 2, t = lane & 3;
    const float* Ab = A  + (long)blockIdx.z * sA + (long)blockIdx.y * 128 * K;
    const float* Bb = Bw + (long)blockIdx.z * sB + (long)blockIdx.x * 128 * ldb;
    const int lr = tid >> 3;             // 0..31
    const int lc = (tid & 7) << 2;       // 0..28

    float acc[4][4][4];
    #pragma unroll
    for (int i = 0; i < 4; i++)
        #pragma unroll
        for (int j = 0; j < 4; j++)
            #pragma unroll
            for (int q = 0; q < 4; q++) acc[i][j][q] = 0.f;

    auto ISSUE = [&](int s, int kt) {
        float* As = AsBase + s * TSLOT;
        float* Bs = BsBase + s * TSLOT;
        #pragma unroll
        for (int r = 0; r < 4; r++) {
            const int row = lr + r * 32;
            cp16((unsigned)__cvta_generic_to_shared(&As[row * TSTRIDE + lc]),
                 &Ab[(long)row * K + kt + lc]);
            cp16((unsigned)__cvta_generic_to_shared(&Bs[row * TSTRIDE + lc]),
                 &Bb[(long)row * ldb + kt + lc]);
        }
        asm volatile("cp.async.commit_group;" ::: "memory");
    };

    auto MM = [&](int s) {
        const float* As = AsBase + s * TSLOT;
        const float* Bs = BsBase + s * TSLOT;
        #pragma unroll
        for (int c = 0; c < 4; c++) {
            const int k0 = c * 8 + t;
            unsigned af[4][4], bf[4][2];
            #pragma unroll
            for (int i = 0; i < 4; i++) {
                const int m = wm * 64 + i * 16 + g;
                af[i][0] = __float_as_uint(As[m * TSTRIDE + k0]);
                af[i][1] = __float_as_uint(As[(m + 8) * TSTRIDE + k0]);
                af[i][2] = __float_as_uint(As[m * TSTRIDE + k0 + 4]);
                af[i][3] = __float_as_uint(As[(m + 8) * TSTRIDE + k0 + 4]);
            }
            #pragma unroll
            for (int j = 0; j < 4; j++) {
                const int n = wn * 32 + j * 8 + g;
                bf[j][0] = __float_as_uint(Bs[n * TSTRIDE + k0]);
                bf[j][1] = __float_as_uint(Bs[n * TSTRIDE + k0 + 4]);
            }
            #pragma unroll
            for (int i = 0; i < 4; i++)
                #pragma unroll
                for (int j = 0; j < 4; j++)
                    asm volatile(
                        "mma.sync.aligned.m16n8k8.row.col.f32.tf32.tf32.f32 "
                        "{%0,%1,%2,%3}, {%4,%5,%6,%7}, {%8,%9}, {%0,%1,%2,%3};\n"
                        : "+f"(acc[i][j][0]), "+f"(acc[i][j][1]),
                          "+f"(acc[i][j][2]), "+f"(acc[i][j][3])
                        : "r"(af[i][0]), "r"(af[i][1]), "r"(af[i][2]), "r"(af[i][3]),
                          "r"(bf[j][0]), "r"(bf[j][1]));
        }
    };

    const int nt = K >> 5;
    ISSUE(0, 0);
    ISSUE(1, 32);
    for (int tt = 0; tt < nt; tt++) {
        if (tt < nt - 1)
            asm volatile("cp.async.wait_group 1;" ::: "memory");
        else
            asm volatile("cp.async.wait_group 0;" ::: "memory");
        __syncthreads();
        MM(tt % 3);
        if (tt + 2 < nt) ISSUE((tt + 2) % 3, (tt + 2) * 32);
    }

    const int gn_base = blockIdx.x * 128 + wn * 32;
    #pragma unroll
    for (int i = 0; i < 4; i++) {
        const long m = (long)blockIdx.y * 128 + wm * 64 + i * 16 + g;
        #pragma unroll
        for (int j = 0; j < 4; j++) {
            const int n0 = gn_base + j * 8 + 2 * t;
            const float b0 = bias ? bias[n0]     : 0.f;
            const float b1 = bias ? bias[n0 + 1] : 0.f;
            const long i0 = (long)blockIdx.z * sC + m * N + n0;
            const long i2 = i0 + 8L * N;
            float x[4] = { acc[i][j][0] * scale + b0, acc[i][j][1] * scale + b1,
                           acc[i][j][2] * scale + b0, acc[i][j][3] * scale + b1 };
            const long idx[4] = { i0, i0 + 1, i2, i2 + 1 };
            float o[4];
            #pragma unroll
            for (int q = 0; q < 4; q++) {
                float xv = x[q];
                if (EPI == 0)      o[q] = xv;
                else if (EPI == 1) o[q] = xv * sigf(xv);
                else if (EPI == 2) o[q] = sigf(xv);
                else if (EPI == 3) o[q] = sigf(xv) * aux1[idx[q]];
                else if (EPI == 4) { float y = xv + aux1[idx[q]]; o[q] = y * sigf(y); }
                else { float s_ = sigf(xv); o[q] = s_ * aux1[idx[q]] + (1.f - s_) * aux2[idx[q]]; }
            }
            float2 w0 = { o[0], o[1] }, w1 = { o[2], o[3] };
            *(float2*)&C[i0] = w0;
            *(float2*)&C[i2] = w1;
        }
    }
}

// ---------------------------------------------------------------------------
// EMA recurrence — batch-grouped (8 groups x 16 CTAs, group owns 2 batches).
// R13 structure + tree-pack reduce-scatter: 16 values reduced with 31 SHFLs
// (vs 80), each sum landing on a distinct lane -> single scattered STS.
// ---------------------------------------------------------------------------
__global__ __launch_bounds__(256, 1)
void ema_rec(const float* __restrict__ bin, const float* __restrict__ pa,
             const float* __restrict__ pd, const float* __restrict__ Wa,
             const float* __restrict__ Wd, float* __restrict__ ema)
{
    __shared__ float prev_s[1024];     // [2 batches][512]
    __shared__ float dot_s[256];       // [2 mats][32 rows][2 batches]
    const int tid  = threadIdx.x;
    const int lane = tid & 31, warp = tid >> 5;
    const int grp   = blockIdx.x >> 4;
    const int j0    = (blockIdx.x & 15) * 32;
    const int bbase = grp * 2;
    const int er = tid & 31, ebI = tid >> 5;    // epilogue map (tid<64)
    float4* prev4 = (float4*)prev_s;
    int* cnt = g_cnt2[grp];

    const float* Wsel = (warp < 4) ? Wa : Wd;
    const int rb = j0 + (warp & 3) * 8;
    unsigned long long wpack[4][16];
    #pragma unroll
    for (int rp = 0; rp < 4; rp++)
        #pragma unroll
        for (int dd = 0; dd < 16; dd++) {
            float wlo = Wsel[(long)(rb + 2*rp)     * 1024 + (dd << 5) + lane];
            float whi = Wsel[(long)(rb + 2*rp + 1) * 1024 + (dd << 5) + lane];
            PACK2(wpack[rp][dd], wlo, whi);
        }

    // precompute reduce-scatter output slot for this lane (even lanes write)
    const int vID = ((lane >> 4) & 1) | (((lane >> 3) & 1) << 1)
                  | (((lane >> 2) & 1) << 2) | (((lane >> 1) & 1) << 3);
    const int v_rp = vID >> 2, v_h = (vID >> 1) & 1, v_b = vID & 1;
    const int dotIdx = ((warp < 4) ? 0 : 128)
                     + ((warp & 3) * 8 + 2 * v_rp + v_h) * 2 + v_b;

    for (int t = 0; t < TT; t++) {
        float bt_v = 0.f, pa_v = 0.f, pd_v = 0.f;
        if (tid < 64) {
            long off = ((long)(bbase + ebI) * TT + t) * DDIM + j0 + er;
            bt_v = bin[off]; pa_v = pa[off]; pd_v = pd[off];
        }
        if (t) {
            if (tid == 0) { while (ldacq(&cnt[t]) < 16) { } }
            __syncthreads();
        }
        const float4* pg = (const float4*)(g_prev[t & 1] + (long)bbase * 512);
        prev4[tid] = __ldcv(pg + tid);
        __syncthreads();

        float pcur = (tid < 64) ? prev_s[ebI * 512 + j0 + er] : 0.f;

        unsigned long long acc2[4][2];
        #pragma unroll
        for (int rp = 0; rp < 4; rp++) { acc2[rp][0] = 0ull; acc2[rp][1] = 0ull; }

        #pragma unroll
        for (int dd = 0; dd < 16; dd++) {
            const int d = (dd << 5) + lane;
            float p0 = prev_s[d];
            float p1 = prev_s[512 + d];
            unsigned long long q0, q1;
            DUP2(q0, p0); DUP2(q1, p1);
            #pragma unroll
            for (int rp = 0; rp < 4; rp++) {
                FMA2(acc2[rp][0], wpack[rp][dd], q0);
                FMA2(acc2[rp][1], wpack[rp][dd], q1);
            }
        }
        // vals[i], i = 4*rp + 2*h + bI  (h = row-within-pair, bI = batch)
        float vals[16];
        #pragma unroll
        for (int rp = 0; rp < 4; rp++) {
            #pragma unroll
            for (int bI = 0; bI < 2; bI++) {
                float lo, hi;
                UNPACK2(lo, hi, acc2[rp][bI]);
                vals[4*rp + bI]     = lo;   // h=0
                vals[4*rp + 2 + bI] = hi;   // h=1
            }
        }
        // tree-pack reduce-scatter: 31 shfl total
        float s8[8];
        #pragma unroll
        for (int j = 0; j < 8; j++) {
            float t0 = vals[2*j]   + __shfl_xor_sync(0xffffffffu, vals[2*j],   16);
            float t1 = vals[2*j+1] + __shfl_xor_sync(0xffffffffu, vals[2*j+1], 16);
            s8[j] = (lane & 16) ? t1 : t0;
        }
        float s4[4];
        #pragma unroll
        for (int j = 0; j < 4; j++) {
            float t0 = s8[2*j]   + __shfl_xor_sync(0xffffffffu, s8[2*j],   8);
            float t1 = s8[2*j+1] + __shfl_xor_sync(0xffffffffu, s8[2*j+1], 8);
            s4[j] = (lane & 8) ? t1 : t0;
        }
        float s2[2];
        #pragma unroll
        for (int j = 0; j < 2; j++) {
            float t0 = s4[2*j]   + __shfl_xor_sync(0xffffffffu, s4[2*j],   4);
            float t1 = s4[2*j+1] + __shfl_xor_sync(0xffffffffu, s4[2*j+1], 4);
            s2[j] = (lane & 4) ? t1 : t0;
        }
        float s1;
        {
            float t0 = s2[0] + __shfl_xor_sync(0xffffffffu, s2[0], 2);
            float t1 = s2[1] + __shfl_xor_sync(0xffffffffu, s2[1], 2);
            s1 = (lane & 2) ? t1 : t0;
        }
        float rsum = s1 + __shfl_xor_sync(0xffffffffu, s1, 1);
        if (!(lane & 1)) dot_s[dotIdx] = rsum;
        __syncthreads();

        if (tid < 64) {
            float alpha = tanhf_fast(dot_s[er * 2 + ebI] + pa_v);
            float delta = tanhf_fast(dot_s[128 + er * 2 + ebI] + pd_v);
            float x = alpha * bt_v + (1.f - alpha * delta) * pcur;
            float e = sigf_fast(x);
            g_prev[(t + 1) & 1][(long)(bbase + ebI) * 512 + j0 + er] = e;
            ema[((long)(bbase + ebI) * TT + t) * DDIM + j0 + er] = e;
        }
        __syncthreads();
        if (tid == 0) redrel(&cnt[t + 1]);
    }
}

extern "C" void kernel_launch(void* const* d_in, const int* in_sizes, int n_in,
                              void* d_out, int out_size) {
    const float* b    = (const float*)d_in[0];
    const float* Wq   = (const float*)d_in[1];
    const float* bq   = (const float*)d_in[2];
    const float* Wk   = (const float*)d_in[3];
    const float* bk   = (const float*)d_in[4];
    const float* Wv   = (const float*)d_in[5];
    const float* bv   = (const float*)d_in[6];
    const float* Wa   = (const float*)d_in[7];
    const float* ba   = (const float*)d_in[8];
    const float* Wd   = (const float*)d_in[9];
    const float* bd   = (const float*)d_in[10];
    const float* Wout = (const float*)d_in[11];
    const float* bout = (const float*)d_in[12];
    const float* W_f  = (const float*)d_in[13];
    const float* b_f  = (const float*)d_in[14];
    const float* W_ec = (const float*)d_in[15];
    const float* W_zc = (const float*)d_in[16];
    const float* b_C  = (const float*)d_in[17];
    const float* W_i  = (const float*)d_in[18];
    const float* b_i  = (const float*)d_in[19];
    const float* W_o  = (const float*)d_in[20];
    const float* b_o  = (const float*)d_in[21];
    float* out = (float*)d_out;

    float* S = nullptr;
    cudaGetSymbolAddress((void**)&S, g_scratch);
    float* pre_a  = S + 0 * PER;
    float* pre_d  = S + 1 * PER;
    float* ema    = S + 2 * PER;
    float* bema   = S + 3 * PER;
    float* q      = S + 4 * PER;
    float* kmat   = S + 5 * PER;
    float* v      = S + 6 * PER;
    float* vT     = S + 7 * PER;
    float* z      = S + 8 * PER;
    float* zf     = S + 9 * PER;
    float* tmpc   = S + 10 * PER;
    float* zc     = S + 11 * PER;
    float* bh     = S + 12 * PER;
    float* scores = S + 13 * PER;
    float* wT1    = scores + 16777216L;
    float* wT2    = wT1 + 262144L;

    cudaFuncSetAttribute(tgemm<0>, cudaFuncAttributeMaxDynamicSharedMemorySize, GSMEM);
    cudaFuncSetAttribute(tgemm<1>, cudaFuncAttributeMaxDynamicSharedMemorySize, GSMEM);
    cudaFuncSetAttribute(tgemm<2>, cudaFuncAttributeMaxDynamicSharedMemorySize, GSMEM);
    cudaFuncSetAttribute(tgemm<3>, cudaFuncAttributeMaxDynamicSharedMemorySize, GSMEM);
    cudaFuncSetAttribute(tgemm<4>, cudaFuncAttributeMaxDynamicSharedMemorySize, GSMEM);
    cudaFuncSetAttribute(tgemm<5>, cudaFuncAttributeMaxDynamicSharedMemorySize, GSMEM);

    const dim3 blk(256);
    const dim3 gD(4, 128, 1);
    const long sBT = (long)TT * DDIM;
    const long sTT = (long)TT * TT;
    const float iscale = 1.f / sqrtf(512.f);

    init_k<<<64, 256>>>();
    transpose_k<<<dim3(16, 16, 1), dim3(32, 8)>>>(W_ec, wT1, 512, 512, 0, 0);
    transpose_k<<<dim3(16, 16, 1), dim3(32, 8)>>>(W_zc, wT2, 512, 512, 0, 0);

    tgemm<0><<<gD, blk, GSMEM>>>(b, Wa + 512, ba, nullptr, nullptr, pre_a, 512, 1024, 512, 0, 0, 0, 1.f);
    tgemm<0><<<gD, blk, GSMEM>>>(b, Wd + 512, bd, nullptr, nullptr, pre_d, 512, 1024, 512, 0, 0, 0, 1.f);

    ema_rec<<<128, 256>>>(b, pre_a, pre_d, Wa, Wd, ema);

    tgemm<1><<<gD, blk, GSMEM>>>(ema, Wout, bout, nullptr, nullptr, bema, 512, 512, 512, 0, 0, 0, 1.f);

    tgemm<0><<<gD, blk, GSMEM>>>(bema, Wq, bq, nullptr, nullptr, q,    512, 512, 512, 0, 0, 0, 1.f);
    tgemm<0><<<gD, blk, GSMEM>>>(bema, Wk, bk, nullptr, nullptr, kmat, 512, 512, 512, 0, 0, 0, 1.f);
    tgemm<0><<<gD, blk, GSMEM>>>(bema, Wv, bv, nullptr, nullptr, v,    512, 512, 512, 0, 0, 0, 1.f);

    tgemm<0><<<dim3(8, 8, 16), blk, GSMEM>>>(q, kmat, nullptr, nullptr, nullptr, scores,
                                             512, 512, 1024, sBT, sBT, sTT, iscale);
    softmax1024<<<BT, 256>>>(scores);

    transpose_k<<<dim3(16, 32, 16), dim3(32, 8)>>>(v, vT, 1024, 512, sBT, sBT);

    tgemm<0><<<dim3(4, 8, 16), blk, GSMEM>>>(scores, vT, nullptr, nullptr, nullptr, z,
                                             1024, 1024, 512, sTT, sBT, sBT, 1.f);

    tgemm<3><<<gD, blk, GSMEM>>>(bema, W_f, b_f, z, nullptr, zf, 512, 512, 512, 0, 0, 0, 1.f);
    tgemm<0><<<gD, blk, GSMEM>>>(bema, wT1, nullptr, nullptr, nullptr, tmpc, 512, 512, 512, 0, 0, 0, 1.f);
    tgemm<4><<<gD, blk, GSMEM>>>(zf, wT2, b_C, tmpc, nullptr, zc, 512, 512, 512, 0, 0, 0, 1.f);
    tgemm<5><<<gD, blk, GSMEM>>>(bema, W_i, b_i, zc, b, bh, 512, 512, 512, 0, 0, 0, 1.f);
    tgemm<2><<<gD, blk, GSMEM>>>(bh, W_o, b_o, nullptr, nullptr, out, 512, 512, 512, 0, 0, 0, 1.f);
}

// round 17
// speedup vs baseline: 2.1119x; 1.0055x over previous
#include <cuda_runtime.h>
#include <math.h>

#define BB 16
#define TT 1024
#define DDIM 512
#define BT (BB*TT)
#define PER ((long)BT*DDIM)

__device__ float g_scratch[13L*PER + 16777216L + 2L*262144L];
__device__ float g_prev[2][BB*DDIM];
__device__ int   g_cnt2[8][TT + 1];    // per-group step counters

__device__ __forceinline__ float sigf(float x) { return 1.f / (1.f + expf(-x)); }
__device__ __forceinline__ float sigf_fast(float x) { return 1.f / (1.f + __expf(-x)); }
__device__ __forceinline__ float tanhf_fast(float x) {
    float e = __expf(2.f * x);
    return 1.f - 2.f / (e + 1.f);
}
__device__ __forceinline__ int ldacq(const int* p) {
    int v; asm volatile("ld.acquire.gpu.global.b32 %0, [%1];" : "=r"(v) : "l"(p) : "memory");
    return v;
}
__device__ __forceinline__ void redrel(int* p) {
    asm volatile("red.release.gpu.global.add.s32 [%0], 1;" :: "l"(p) : "memory");
}
__device__ __forceinline__ void cp16(unsigned saddr, const void* g) {
    asm volatile("cp.async.ca.shared.global [%0], [%1], 16;" :: "r"(saddr), "l"(g));
}
#define FMA2(a,b,c) asm("fma.rn.f32x2 %0, %1, %2, %0;" : "+l"(a) : "l"(b), "l"(c))
#define DUP2(o,x)   asm("mov.b64 %0, {%1,%1};" : "=l"(o) : "r"(__float_as_uint(x)))
#define PACK2(o,lo,hi) asm("mov.b64 %0, {%1,%2};" : "=l"(o) : "r"(__float_as_uint(lo)), "r"(__float_as_uint(hi)))
#define UNPACK2(lo,hi,a) do { unsigned _l,_h; \
    asm("mov.b64 {%0,%1}, %2;" : "=r"(_l), "=r"(_h) : "l"(a)); \
    lo = __uint_as_float(_l); hi = __uint_as_float(_h); } while(0)

__global__ void init_k() {
    int tid = blockIdx.x * blockDim.x + threadIdx.x;
    if (tid < BB*DDIM) g_prev[0][tid] = 0.f;
    if (tid < 8 * (TT + 1)) ((int*)g_cnt2)[tid] = 0;
}

// in [Z,R,C] -> out [Z,C,R]
__global__ void transpose_k(const float* __restrict__ in, float* __restrict__ out,
                            int R, int C, long sIn, long sOut) {
    __shared__ float tile[32][33];
    const float* ib = in  + (long)blockIdx.z * sIn;
    float*       ob = out + (long)blockIdx.z * sOut;
    int c0 = blockIdx.x * 32, r0 = blockIdx.y * 32;
    for (int i = threadIdx.y; i < 32; i += 8)
        tile[i][threadIdx.x] = ib[(long)(r0 + i) * C + c0 + threadIdx.x];
    __syncthreads();
    for (int i = threadIdx.y; i < 32; i += 8)
        ob[(long)(c0 + i) * R + r0 + threadIdx.x] = tile[threadIdx.x][i];
}

__global__ void softmax1024(float* __restrict__ data) {
    __shared__ float red[8];
    int tid = threadIdx.x;
    float4* p = ((float4*)data) + ((long)blockIdx.x << 8);
    float4 v = p[tid];
    float m = fmaxf(fmaxf(v.x, v.y), fmaxf(v.z, v.w));
    #pragma unroll
    for (int o = 16; o; o >>= 1) m = fmaxf(m, __shfl_xor_sync(0xffffffffu, m, o));
    if ((tid & 31) == 0) red[tid >> 5] = m;
    __syncthreads();
    m = red[0];
    #pragma unroll
    for (int i = 1; i < 8; i++) m = fmaxf(m, red[i]);
    v.x = __expf(v.x - m); v.y = __expf(v.y - m);
    v.z = __expf(v.z - m); v.w = __expf(v.w - m);
    float s = v.x + v.y + v.z + v.w;
    #pragma unroll
    for (int o = 16; o; o >>= 1) s += __shfl_xor_sync(0xffffffffu, s, o);
    __syncthreads();
    if ((tid & 31) == 0) red[tid >> 5] = s;
    __syncthreads();
    s = red[0];
    #pragma unroll
    for (int i = 1; i < 8; i++) s += red[i];
    float inv = 1.f / s;
    v.x *= inv; v.y *= inv; v.z *= inv; v.w *= inv;
    p[tid] = v;
}

// ---------------------------------------------------------------------------
// tf32 tensor-core NT GEMM, cp.async 3-stage pipeline, K-chunk 32 (proven).
// ---------------------------------------------------------------------------
#define TSTRIDE 36
#define TSLOT (128 * TSTRIDE)
#define GSMEM (6 * TSLOT * 4)

template<int EPI>
__global__ __launch_bounds__(256)
void tgemm(const float* __restrict__ A, const float* __restrict__ Bw,
           const float* __restrict__ bias,
           const float* __restrict__ aux1, const float* __restrict__ aux2,
           float* __restrict__ C,
           int K, int ldb, int N, long sA, long sB, long sC, float scale)
{
    extern __shared__ float smem[];
    float* AsBase = smem;
    float* BsBase = smem + 3 * TSLOT;
    const int tid  = threadIdx.x;
    const int lane = tid & 31, warp = tid >> 5;
    const int wm = warp >> 2, wn = warp & 3;
    const int g = lane >> 2, t = lane & 3;
    const float* Ab = A  + (long)blockIdx.z * sA + (long)blockIdx.y * 128 * K;
    const float* Bb = Bw + (long)blockIdx.z * sB + (long)blockIdx.x * 128 * ldb;
    const int lr = tid >> 3;
    const int lc = (tid & 7) << 2;

    float acc[4][4][4];
    #pragma unroll
    for (int i = 0; i < 4; i++)
        #pragma unroll
        for (int j = 0; j < 4; j++)
            #pragma unroll
            for (int q = 0; q < 4; q++) acc[i][j][q] = 0.f;

    auto ISSUE = [&](int s, int kt) {
        float* As = AsBase + s * TSLOT;
        float* Bs = BsBase + s * TSLOT;
        #pragma unroll
        for (int r = 0; r < 4; r++) {
            const int row = lr + r * 32;
            cp16((unsigned)__cvta_generic_to_shared(&As[row * TSTRIDE + lc]),
                 &Ab[(long)row * K + kt + lc]);
            cp16((unsigned)__cvta_generic_to_shared(&Bs[row * TSTRIDE + lc]),
                 &Bb[(long)row * ldb + kt + lc]);
        }
        asm volatile("cp.async.commit_group;" ::: "memory");
    };

    auto MM = [&](int s) {
        const float* As = AsBase + s * TSLOT;
        const float* Bs = BsBase + s * TSLOT;
        #pragma unroll
        for (int c = 0; c < 4; c++) {
            const int k0 = c * 8 + t;
            unsigned af[4][4], bf[4][2];
            #pragma unroll
            for (int i = 0; i < 4; i++) {
                const int m = wm * 64 + i * 16 + g;
                af[i][0] = __float_as_uint(As[m * TSTRIDE + k0]);
                af[i][1] = __float_as_uint(As[(m + 8) * TSTRIDE + k0]);
                af[i][2] = __float_as_uint(As[m * TSTRIDE + k0 + 4]);
                af[i][3] = __float_as_uint(As[(m + 8) * TSTRIDE + k0 + 4]);
            }
            #pragma unroll
            for (int j = 0; j < 4; j++) {
                const int n = wn * 32 + j * 8 + g;
                bf[j][0] = __float_as_uint(Bs[n * TSTRIDE + k0]);
                bf[j][1] = __float_as_uint(Bs[n * TSTRIDE + k0 + 4]);
            }
            #pragma unroll
            for (int i = 0; i < 4; i++)
                #pragma unroll
                for (int j = 0; j < 4; j++)
                    asm volatile(
                        "mma.sync.aligned.m16n8k8.row.col.f32.tf32.tf32.f32 "
                        "{%0,%1,%2,%3}, {%4,%5,%6,%7}, {%8,%9}, {%0,%1,%2,%3};\n"
                        : "+f"(acc[i][j][0]), "+f"(acc[i][j][1]),
                          "+f"(acc[i][j][2]), "+f"(acc[i][j][3])
                        : "r"(af[i][0]), "r"(af[i][1]), "r"(af[i][2]), "r"(af[i][3]),
                          "r"(bf[j][0]), "r"(bf[j][1]));
        }
    };

    const int nt = K >> 5;
    ISSUE(0, 0);
    ISSUE(1, 32);
    for (int tt = 0; tt < nt; tt++) {
        if (tt < nt - 1)
            asm volatile("cp.async.wait_group 1;" ::: "memory");
        else
            asm volatile("cp.async.wait_group 0;" ::: "memory");
        __syncthreads();
        MM(tt % 3);
        if (tt + 2 < nt) ISSUE((tt + 2) % 3, (tt + 2) * 32);
    }

    const int gn_base = blockIdx.x * 128 + wn * 32;
    #pragma unroll
    for (int i = 0; i < 4; i++) {
        const long m = (long)blockIdx.y * 128 + wm * 64 + i * 16 + g;
        #pragma unroll
        for (int j = 0; j < 4; j++) {
            const int n0 = gn_base + j * 8 + 2 * t;
            const float b0 = bias ? bias[n0]     : 0.f;
            const float b1 = bias ? bias[n0 + 1] : 0.f;
            const long i0 = (long)blockIdx.z * sC + m * N + n0;
            const long i2 = i0 + 8L * N;
            float x[4] = { acc[i][j][0] * scale + b0, acc[i][j][1] * scale + b1,
                           acc[i][j][2] * scale + b0, acc[i][j][3] * scale + b1 };
            const long idx[4] = { i0, i0 + 1, i2, i2 + 1 };
            float o[4];
            #pragma unroll
            for (int q = 0; q < 4; q++) {
                float xv = x[q];
                if (EPI == 0)      o[q] = xv;
                else if (EPI == 1) o[q] = xv * sigf(xv);
                else if (EPI == 2) o[q] = sigf(xv);
                else if (EPI == 3) o[q] = sigf(xv) * aux1[idx[q]];
                else if (EPI == 4) { float y = xv + aux1[idx[q]]; o[q] = y * sigf(y); }
                else { float s_ = sigf(xv); o[q] = s_ * aux1[idx[q]] + (1.f - s_) * aux2[idx[q]]; }
            }
            float2 w0 = { o[0], o[1] }, w1 = { o[2], o[3] };
            *(float2*)&C[i0] = w0;
            *(float2*)&C[i2] = w1;
        }
    }
}

// ---------------------------------------------------------------------------
// EMA recurrence — batch-grouped (8 groups x 16 CTAs), R14's PROVEN
// release/acquire flag protocol. Single change vs R14: the trailing
// __syncthreads + tid0-redrel is replaced by per-producer-warp arrival
// (warps 0,1: __syncwarp fence over own 32 state stores, then lane0
// red.release +1). Consumer waits for 32 arrivals (2 per CTA).
// f32x2 dot core + 31-SHFL tree reduce-scatter (proven R14, bitwise same).
// ---------------------------------------------------------------------------
__global__ __launch_bounds__(256, 1)
void ema_rec(const float* __restrict__ bin, const float* __restrict__ pa,
             const float* __restrict__ pd, const float* __restrict__ Wa,
             const float* __restrict__ Wd, float* __restrict__ ema)
{
    __shared__ float prev_s[1024];     // [2 batches][512]
    __shared__ float dot_s[256];       // [2 mats][32 rows][2 batches]
    const int tid  = threadIdx.x;
    const int lane = tid & 31, warp = tid >> 5;
    const int grp   = blockIdx.x >> 4;
    const int j0    = (blockIdx.x & 15) * 32;
    const int bbase = grp * 2;
    const int er = tid & 31, ebI = tid >> 5;    // epilogue map (tid<64)
    float4* prev4 = (float4*)prev_s;
    int* cnt = g_cnt2[grp];

    const float* Wsel = (warp < 4) ? Wa : Wd;
    const int rb = j0 + (warp & 3) * 8;
    unsigned long long wpack[4][16];
    #pragma unroll
    for (int rp = 0; rp < 4; rp++)
        #pragma unroll
        for (int dd = 0; dd < 16; dd++) {
            float wlo = Wsel[(long)(rb + 2*rp)     * 1024 + (dd << 5) + lane];
            float whi = Wsel[(long)(rb + 2*rp + 1) * 1024 + (dd << 5) + lane];
            PACK2(wpack[rp][dd], wlo, whi);
        }

    // reduce-scatter output slot (even lanes write)
    const int vID = ((lane >> 4) & 1) | (((lane >> 3) & 1) << 1)
                  | (((lane >> 2) & 1) << 2) | (((lane >> 1) & 1) << 3);
    const int v_rp = vID >> 2, v_h = (vID >> 1) & 1, v_b = vID & 1;
    const int dotIdx = ((warp < 4) ? 0 : 128)
                     + ((warp & 3) * 8 + 2 * v_rp + v_h) * 2 + v_b;

    // this thread's producer location (tid<64)
    const long myOut = (long)(bbase + ebI) * 512 + j0 + er;

    for (int t = 0; t < TT; t++) {
        float bt_v = 0.f, pa_v = 0.f, pd_v = 0.f;
        if (tid < 64) {
            long off = ((long)(bbase + ebI) * TT + t) * DDIM + j0 + er;
            bt_v = bin[off]; pa_v = pa[off]; pd_v = pd[off];
        }
        if (t) {
            if (tid == 0) { while (ldacq(&cnt[t]) < 32) { } }
            __syncthreads();   // bar1: flag observed -> safe to stage
        }
        const float4* pg = (const float4*)(g_prev[t & 1] + (long)bbase * 512);
        prev4[tid] = __ldcv(pg + tid);
        __syncthreads();       // bar2: staging complete

        float pcur = (tid < 64) ? prev_s[ebI * 512 + j0 + er] : 0.f;

        unsigned long long acc2[4][2];
        #pragma unroll
        for (int rp = 0; rp < 4; rp++) { acc2[rp][0] = 0ull; acc2[rp][1] = 0ull; }

        #pragma unroll
        for (int dd = 0; dd < 16; dd++) {
            const int d = (dd << 5) + lane;
            float p0 = prev_s[d];
            float p1 = prev_s[512 + d];
            unsigned long long q0, q1;
            DUP2(q0, p0); DUP2(q1, p1);
            #pragma unroll
            for (int rp = 0; rp < 4; rp++) {
                FMA2(acc2[rp][0], wpack[rp][dd], q0);
                FMA2(acc2[rp][1], wpack[rp][dd], q1);
            }
        }
        float vals[16];
        #pragma unroll
        for (int rp = 0; rp < 4; rp++) {
            #pragma unroll
            for (int bI = 0; bI < 2; bI++) {
                float lo2, hi2;
                UNPACK2(lo2, hi2, acc2[rp][bI]);
                vals[4*rp + bI]     = lo2;
                vals[4*rp + 2 + bI] = hi2;
            }
        }
        float s8[8];
        #pragma unroll
        for (int j = 0; j < 8; j++) {
            float t0 = vals[2*j]   + __shfl_xor_sync(0xffffffffu, vals[2*j],   16);
            float t1 = vals[2*j+1] + __shfl_xor_sync(0xffffffffu, vals[2*j+1], 16);
            s8[j] = (lane & 16) ? t1 : t0;
        }
        float s4[4];
        #pragma unroll
        for (int j = 0; j < 4; j++) {
            float t0 = s8[2*j]   + __shfl_xor_sync(0xffffffffu, s8[2*j],   8);
            float t1 = s8[2*j+1] + __shfl_xor_sync(0xffffffffu, s8[2*j+1], 8);
            s4[j] = (lane & 8) ? t1 : t0;
        }
        float s2[2];
        #pragma unroll
        for (int j = 0; j < 2; j++) {
            float t0 = s4[2*j]   + __shfl_xor_sync(0xffffffffu, s4[2*j],   4);
            float t1 = s4[2*j+1] + __shfl_xor_sync(0xffffffffu, s4[2*j+1], 4);
            s2[j] = (lane & 4) ? t1 : t0;
        }
        float s1;
        {
            float t0 = s2[0] + __shfl_xor_sync(0xffffffffu, s2[0], 2);
            float t1 = s2[1] + __shfl_xor_sync(0xffffffffu, s2[1], 2);
            s1 = (lane & 2) ? t1 : t0;
        }
        float rsum = s1 + __shfl_xor_sync(0xffffffffu, s1, 1);
        if (!(lane & 1)) dot_s[dotIdx] = rsum;
        __syncthreads();       // bar3: dot_s ready (also fences prev_s reuse)

        if (tid < 64) {
            float alpha = tanhf_fast(dot_s[er * 2 + ebI] + pa_v);
            float delta = tanhf_fast(dot_s[128 + er * 2 + ebI] + pd_v);
            float x = alpha * bt_v + (1.f - alpha * delta) * pcur;
            float e = sigf_fast(x);
            __stcg(&g_prev[(t + 1) & 1][myOut], e);
            ema[((long)(bbase + ebI) * TT + t) * DDIM + j0 + er] = e;
        }
        // per-producer-warp arrival: warp-scope fence over this warp's 32
        // state stores, then gpu-scope release increment. 2 arrivals/CTA.
        if (warp < 2) {
            __syncwarp();
            if (lane == 0) redrel(&cnt[t + 1]);
        }
        // no trailing CTA bar: next dot_s writes gated by next bar2; next
        // prev_s stage gated by next bar1; epilogue reads precede bar1(t+1).
    }
}

extern "C" void kernel_launch(void* const* d_in, const int* in_sizes, int n_in,
                              void* d_out, int out_size) {
    const float* b    = (const float*)d_in[0];
    const float* Wq   = (const float*)d_in[1];
    const float* bq   = (const float*)d_in[2];
    const float* Wk   = (const float*)d_in[3];
    const float* bk   = (const float*)d_in[4];
    const float* Wv   = (const float*)d_in[5];
    const float* bv   = (const float*)d_in[6];
    const float* Wa   = (const float*)d_in[7];
    const float* ba   = (const float*)d_in[8];
    const float* Wd   = (const float*)d_in[9];
    const float* bd   = (const float*)d_in[10];
    const float* Wout = (const float*)d_in[11];
    const float* bout = (const float*)d_in[12];
    const float* W_f  = (const float*)d_in[13];
    const float* b_f  = (const float*)d_in[14];
    const float* W_ec = (const float*)d_in[15];
    const float* W_zc = (const float*)d_in[16];
    const float* b_C  = (const float*)d_in[17];
    const float* W_i  = (const float*)d_in[18];
    const float* b_i  = (const float*)d_in[19];
    const float* W_o  = (const float*)d_in[20];
    const float* b_o  = (const float*)d_in[21];
    float* out = (float*)d_out;

    float* S = nullptr;
    cudaGetSymbolAddress((void**)&S, g_scratch);
    float* pre_a  = S + 0 * PER;
    float* pre_d  = S + 1 * PER;
    float* ema    = S + 2 * PER;
    float* bema   = S + 3 * PER;
    float* q      = S + 4 * PER;
    float* kmat   = S + 5 * PER;
    float* v      = S + 6 * PER;
    float* vT     = S + 7 * PER;
    float* z      = S + 8 * PER;
    float* zf     = S + 9 * PER;
    float* tmpc   = S + 10 * PER;
    float* zc     = S + 11 * PER;
    float* bh     = S + 12 * PER;
    float* scores = S + 13 * PER;
    float* wT1    = scores + 16777216L;
    float* wT2    = wT1 + 262144L;

    cudaFuncSetAttribute(tgemm<0>, cudaFuncAttributeMaxDynamicSharedMemorySize, GSMEM);
    cudaFuncSetAttribute(tgemm<1>, cudaFuncAttributeMaxDynamicSharedMemorySize, GSMEM);
    cudaFuncSetAttribute(tgemm<2>, cudaFuncAttributeMaxDynamicSharedMemorySize, GSMEM);
    cudaFuncSetAttribute(tgemm<3>, cudaFuncAttributeMaxDynamicSharedMemorySize, GSMEM);
    cudaFuncSetAttribute(tgemm<4>, cudaFuncAttributeMaxDynamicSharedMemorySize, GSMEM);
    cudaFuncSetAttribute(tgemm<5>, cudaFuncAttributeMaxDynamicSharedMemorySize, GSMEM);

    const dim3 blk(256);
    const dim3 gD(4, 128, 1);
    const long sBT = (long)TT * DDIM;
    const long sTT = (long)TT * TT;
    const float iscale = 1.f / sqrtf(512.f);

    init_k<<<64, 256>>>();
    transpose_k<<<dim3(16, 16, 1), dim3(32, 8)>>>(W_ec, wT1, 512, 512, 0, 0);
    transpose_k<<<dim3(16, 16, 1), dim3(32, 8)>>>(W_zc, wT2, 512, 512, 0, 0);

    tgemm<0><<<gD, blk, GSMEM>>>(b, Wa + 512, ba, nullptr, nullptr, pre_a, 512, 1024, 512, 0, 0, 0, 1.f);
    tgemm<0><<<gD, blk, GSMEM>>>(b, Wd + 512, bd, nullptr, nullptr, pre_d, 512, 1024, 512, 0, 0, 0, 1.f);

    ema_rec<<<128, 256>>>(b, pre_a, pre_d, Wa, Wd, ema);

    tgemm<1><<<gD, blk, GSMEM>>>(ema, Wout, bout, nullptr, nullptr, bema, 512, 512, 512, 0, 0, 0, 1.f);

    tgemm<0><<<gD, blk, GSMEM>>>(bema, Wq, bq, nullptr, nullptr, q,    512, 512, 512, 0, 0, 0, 1.f);
    tgemm<0><<<gD, blk, GSMEM>>>(bema, Wk, bk, nullptr, nullptr, kmat, 512, 512, 512, 0, 0, 0, 1.f);
    tgemm<0><<<gD, blk, GSMEM>>>(bema, Wv, bv, nullptr, nullptr, v,    512, 512, 512, 0, 0, 0, 1.f);

    tgemm<0><<<dim3(8, 8, 16), blk, GSMEM>>>(q, kmat, nullptr, nullptr, nullptr, scores,
                                             512, 512, 1024, sBT, sBT, sTT, iscale);
    softmax1024<<<BT, 256>>>(scores);

    transpose_k<<<dim3(16, 32, 16), dim3(32, 8)>>>(v, vT, 1024, 512, sBT, sBT);

    tgemm<0><<<dim3(4, 8, 16), blk, GSMEM>>>(scores, vT, nullptr, nullptr, nullptr, z,
                                             1024, 1024, 512, sTT, sBT, sBT, 1.f);

    tgemm<3><<<gD, blk, GSMEM>>>(bema, W_f, b_f, z, nullptr, zf, 512, 512, 512, 0, 0, 0, 1.f);
    tgemm<0><<<gD, blk, GSMEM>>>(bema, wT1, nullptr, nullptr, nullptr, tmpc, 512, 512, 512, 0, 0, 0, 1.f);
    tgemm<4><<<gD, blk, GSMEM>>>(zf, wT2, b_C, tmpc, nullptr, zc, 512, 512, 512, 0, 0, 0, 1.f);
    tgemm<5><<<gD, blk, GSMEM>>>(bema, W_i, b_i, zc, b, bh, 512, 512, 512, 0, 0, 0, 1.f);
    tgemm<2><<<gD, blk, GSMEM>>>(bh, W_o, b_o, nullptr, nullptr, out, 512, 512, 512, 0, 0, 0, 1.f);
}